// round 1
// baseline (speedup 1.0000x reference)
#include <cuda_runtime.h>
#include <math.h>

// Problem dims
#define Bn   16384
#define Tn   3
#define Dn   512
#define Gn   4
#define NEn  4
#define NEXP 16      // G * NE
#define Hn   512
#define En   256
#define GHn  256
#define THn  128
#define TOn  64

// Scratch (static device globals -- allocation-free per harness rules)
__device__ float g_gin[(size_t)Bn * Tn * Dn];        // [B,T,D]     96 MB
__device__ float g_h1 [(size_t)Bn * NEXP * Hn];      // [B,16,H]   512 MB
__device__ float g_emb[(size_t)Bn * NEXP * En];      // [B,16,E]   256 MB
__device__ float g_gh [(size_t)Bn * Tn * GHn];       // [B,T,GH]    48 MB
__device__ float g_gw [(size_t)Bn * Tn * NEXP];      // [B,T,16]     3 MB
__device__ float g_agg[(size_t)Bn * Tn * En];        // [B,T,E]     48 MB
__device__ float g_th [(size_t)Bn * Tn * THn];       // [B,T,TH]    24 MB

// ---------------------------------------------------------------------------
// gin[b,t,:] = inputs[b,t+1,:] + inputs[b,0,:]
// ---------------------------------------------------------------------------
__global__ void gin_kernel(const float* __restrict__ in) {
    int idx = blockIdx.x * blockDim.x + threadIdx.x;   // over B*T*D/4 float4s
    int total = Bn * Tn * Dn / 4;
    if (idx >= total) return;
    int d4 = idx % (Dn / 4);
    int bt = idx / (Dn / 4);
    int t  = bt % Tn;
    int b  = bt / Tn;
    const float4* base = (const float4*)(in + (size_t)b * Gn * Dn);
    float4 a = base[(size_t)(t + 1) * (Dn / 4) + d4];
    float4 s = base[d4];
    float4 r = make_float4(a.x + s.x, a.y + s.y, a.z + s.z, a.w + s.w);
    ((float4*)g_gin)[idx] = r;
}

// ---------------------------------------------------------------------------
// Batched SGEMM with bias + optional relu.
// C[b-th row, col] = A[row,:K] @ Bw[:K,col] + bias[col]
// Per-z offsets: A += (z/aDiv)*aStride, Bw += z*bStride, bias += z*biasStride,
//                C += z*cStride.  M = gridDim.x * 128 (always exact here).
// 128x128 block tile, BK=8, 256 threads, 8x8 per thread.
// ---------------------------------------------------------------------------
#define BM 128
#define BN 128
#define BK 8
#define TM 8
#define TN 8

__global__ __launch_bounds__(256)
void sgemm_bias(const float* __restrict__ A, const float* __restrict__ Bw,
                const float* __restrict__ bias, float* __restrict__ C,
                int N, int K, int lda, int ldb, int ldc,
                long aStride, int aDiv, long bStride, long biasStride, long cStride,
                int relu)
{
    int z = blockIdx.z;
    A    += (long)(z / aDiv) * aStride;
    Bw   += (long)z * bStride;
    bias += (long)z * biasStride;
    C    += (long)z * cStride;

    __shared__ float As[BK][BM];
    __shared__ float Bs[BK][BN];

    int tid  = threadIdx.x;
    int row0 = blockIdx.x * BM;
    int col0 = blockIdx.y * BN;
    int tx = tid % 16;          // 16 col-threads
    int ty = tid / 16;          // 16 row-threads

    // A tile load mapping: 128 rows x 8 k, one float4 per thread along K
    int aRow = tid >> 1;
    int aCol = (tid & 1) * 4;
    // B tile load mapping: 8 k-rows x 128 cols, one float4 per thread along N
    int bRow = tid >> 5;
    int bCol = (tid & 31) * 4;
    bool bOk = (col0 + bCol) < N;

    float acc[TM][TN];
    #pragma unroll
    for (int i = 0; i < TM; i++)
        #pragma unroll
        for (int j = 0; j < TN; j++) acc[i][j] = 0.0f;

    for (int k0 = 0; k0 < K; k0 += BK) {
        float4 av = *(const float4*)&A[(long)(row0 + aRow) * lda + k0 + aCol];
        As[aCol + 0][aRow] = av.x;
        As[aCol + 1][aRow] = av.y;
        As[aCol + 2][aRow] = av.z;
        As[aCol + 3][aRow] = av.w;
        if (bOk) {
            float4 bv = *(const float4*)&Bw[(long)(k0 + bRow) * ldb + col0 + bCol];
            *(float4*)&Bs[bRow][bCol] = bv;
        }
        __syncthreads();

        #pragma unroll
        for (int kk = 0; kk < BK; kk++) {
            float4 a0 = *(const float4*)&As[kk][ty * TM];
            float4 a1 = *(const float4*)&As[kk][ty * TM + 4];
            float4 b0 = *(const float4*)&Bs[kk][tx * TN];
            float4 b1 = *(const float4*)&Bs[kk][tx * TN + 4];
            float ra[TM] = {a0.x, a0.y, a0.z, a0.w, a1.x, a1.y, a1.z, a1.w};
            float rb[TN] = {b0.x, b0.y, b0.z, b0.w, b1.x, b1.y, b1.z, b1.w};
            #pragma unroll
            for (int i = 0; i < TM; i++)
                #pragma unroll
                for (int j = 0; j < TN; j++)
                    acc[i][j] += ra[i] * rb[j];
        }
        __syncthreads();
    }

    #pragma unroll
    for (int i = 0; i < TM; i++) {
        long r = row0 + ty * TM + i;
        #pragma unroll
        for (int j0 = 0; j0 < TN; j0 += 4) {
            int c = col0 + tx * TN + j0;
            if (c < N) {
                float4 v;
                v.x = acc[i][j0 + 0] + bias[c + 0];
                v.y = acc[i][j0 + 1] + bias[c + 1];
                v.z = acc[i][j0 + 2] + bias[c + 2];
                v.w = acc[i][j0 + 3] + bias[c + 3];
                if (relu) {
                    v.x = fmaxf(v.x, 0.f); v.y = fmaxf(v.y, 0.f);
                    v.z = fmaxf(v.z, 0.f); v.w = fmaxf(v.w, 0.f);
                }
                *(float4*)&C[r * ldc + c] = v;
            }
        }
    }
}

// ---------------------------------------------------------------------------
// Gate layer 2 + softmax: gw[b,t,:] = softmax(gh[b,t,:] @ W2[t] + b2[t])
// One thread per (b) row, blockIdx.y = task; W2[t] staged in smem.
// ---------------------------------------------------------------------------
__global__ void gate2_softmax_kernel(const float* __restrict__ W2,
                                     const float* __restrict__ b2) {
    int t = blockIdx.y;
    __shared__ float sW[GHn * NEXP];   // 16 KB
    __shared__ float sb[NEXP];
    for (int i = threadIdx.x; i < GHn * NEXP; i += blockDim.x)
        sW[i] = W2[(size_t)t * GHn * NEXP + i];
    if (threadIdx.x < NEXP) sb[threadIdx.x] = b2[t * NEXP + threadIdx.x];
    __syncthreads();

    int b = blockIdx.x * blockDim.x + threadIdx.x;
    if (b >= Bn) return;

    const float4* gr = (const float4*)(g_gh + ((size_t)b * Tn + t) * GHn);
    float acc[NEXP];
    #pragma unroll
    for (int k = 0; k < NEXP; k++) acc[k] = sb[k];
    for (int h4 = 0; h4 < GHn / 4; h4++) {
        float4 x = gr[h4];
        const float* w = sW + h4 * 4 * NEXP;
        #pragma unroll
        for (int k = 0; k < NEXP; k++)
            acc[k] += x.x * w[k] + x.y * w[NEXP + k]
                    + x.z * w[2 * NEXP + k] + x.w * w[3 * NEXP + k];
    }
    float mx = acc[0];
    #pragma unroll
    for (int k = 1; k < NEXP; k++) mx = fmaxf(mx, acc[k]);
    float sum = 0.f;
    #pragma unroll
    for (int k = 0; k < NEXP; k++) { acc[k] = expf(acc[k] - mx); sum += acc[k]; }
    float inv = 1.0f / sum;
    float* o = g_gw + ((size_t)b * Tn + t) * NEXP;
    #pragma unroll
    for (int k = 0; k < NEXP; k++) o[k] = acc[k] * inv;
}

// ---------------------------------------------------------------------------
// agg[b,t,:] = sum_k gw[b,t,k] * emb[b,k,:]   (all 3 tasks, emb read once)
// One block per b, 256 threads = E columns.
// ---------------------------------------------------------------------------
__global__ void agg_kernel() {
    int b = blockIdx.x;
    int e = threadIdx.x;
    __shared__ float sgw[Tn * NEXP];
    if (threadIdx.x < Tn * NEXP)
        sgw[threadIdx.x] = g_gw[(size_t)b * Tn * NEXP + threadIdx.x];
    __syncthreads();
    const float* eb = g_emb + (size_t)b * NEXP * En + e;
    float a0 = 0.f, a1 = 0.f, a2 = 0.f;
    #pragma unroll
    for (int k = 0; k < NEXP; k++) {
        float v = eb[(size_t)k * En];
        a0 += sgw[k] * v;
        a1 += sgw[NEXP + k] * v;
        a2 += sgw[2 * NEXP + k] * v;
    }
    float* o = g_agg + (size_t)b * Tn * En + e;
    o[0]      = a0;
    o[En]     = a1;
    o[2 * En] = a2;
}

// ---------------------------------------------------------------------------
extern "C" void kernel_launch(void* const* d_in, const int* in_sizes, int n_in,
                              void* d_out, int out_size) {
    const float* inputs = (const float*)d_in[0];
    const float* eW1 = (const float*)d_in[1];
    const float* eb1 = (const float*)d_in[2];
    const float* eW2 = (const float*)d_in[3];
    const float* eb2 = (const float*)d_in[4];
    const float* gW1 = (const float*)d_in[5];
    const float* gb1 = (const float*)d_in[6];
    const float* gW2 = (const float*)d_in[7];
    const float* gb2 = (const float*)d_in[8];
    const float* tW1 = (const float*)d_in[9];
    const float* tb1 = (const float*)d_in[10];
    const float* tW2 = (const float*)d_in[11];
    const float* tb2 = (const float*)d_in[12];
    float* out = (float*)d_out;

    float *p_gin, *p_h1, *p_emb, *p_gh, *p_agg, *p_th;
    cudaGetSymbolAddress((void**)&p_gin, g_gin);
    cudaGetSymbolAddress((void**)&p_h1,  g_h1);
    cudaGetSymbolAddress((void**)&p_emb, g_emb);
    cudaGetSymbolAddress((void**)&p_gh,  g_gh);
    cudaGetSymbolAddress((void**)&p_agg, g_agg);
    cudaGetSymbolAddress((void**)&p_th,  g_th);

    // gate input = task input + shared input
    gin_kernel<<<(Bn * Tn * Dn / 4 + 255) / 256, 256>>>(inputs);

    // expert layer 1: h1[b,e16,:] = relu(inputs[b, e16/4, :] @ eW1[e16] + eb1[e16])
    sgemm_bias<<<dim3(Bn / BM, Hn / BN, NEXP), 256>>>(
        inputs, eW1, eb1, p_h1,
        Hn, Dn, Gn * Dn, Hn, NEXP * Hn,
        (long)Dn, NEn, (long)Dn * Hn, (long)Hn, (long)Hn, 1);

    // expert layer 2: emb[b,e16,:] = h1[b,e16,:] @ eW2[e16] + eb2[e16]
    sgemm_bias<<<dim3(Bn / BM, En / BN, NEXP), 256>>>(
        p_h1, eW2, eb2, p_emb,
        En, Hn, NEXP * Hn, En, NEXP * En,
        (long)Hn, 1, (long)Hn * En, (long)En, (long)En, 0);

    // gate layer 1: gh[b,t,:] = relu(gin[b,t,:] @ gW1[t] + gb1[t])
    sgemm_bias<<<dim3(Bn / BM, GHn / BN, Tn), 256>>>(
        p_gin, gW1, gb1, p_gh,
        GHn, Dn, Tn * Dn, GHn, Tn * GHn,
        (long)Dn, 1, (long)Dn * GHn, (long)GHn, (long)GHn, 1);

    // gate layer 2 + softmax
    gate2_softmax_kernel<<<dim3(Bn / 256, Tn), 256>>>(gW2, gb2);

    // weighted expert aggregation
    agg_kernel<<<Bn, En>>>();

    // tower layer 1: th[b,t,:] = relu(agg[b,t,:] @ tW1[t] + tb1[t])
    sgemm_bias<<<dim3(Bn / BM, 1, Tn), 256>>>(
        p_agg, tW1, tb1, p_th,
        THn, En, Tn * En, THn, Tn * THn,
        (long)En, 1, (long)En * THn, (long)THn, (long)THn, 1);

    // tower layer 2 -> final output [B, T*TO]
    sgemm_bias<<<dim3(Bn / BM, 1, Tn), 256>>>(
        p_th, tW2, tb2, out,
        TOn, THn, Tn * THn, TOn, Tn * TOn,
        (long)THn, 1, (long)THn * TOn, (long)TOn, (long)TOn, 0);
}

// round 3
// speedup vs baseline: 1.0455x; 1.0455x over previous
#include <cuda_runtime.h>
#include <cuda_bf16.h>
#include <cstdint>
#include <math.h>

// Problem dims
#define Bn   16384
#define Tn   3
#define Dn   512
#define Gn   4
#define NEn  4
#define NEXP 16      // G * NE
#define Hn   512
#define En   256
#define GHn  256
#define THn  128
#define TOn  64

// Scratch (static device globals -- allocation-free per harness rules)
__device__ float g_gin[(size_t)Bn * Tn * Dn];        // [B,T,D]     96 MB
__device__ float g_h1 [(size_t)Bn * NEXP * Hn];      // [B,16,H]   512 MB
__device__ float g_emb[(size_t)Bn * NEXP * En];      // [B,16,E]   256 MB
__device__ float g_gh [(size_t)Bn * Tn * GHn];       // [B,T,GH]    48 MB
__device__ float g_gw [(size_t)Bn * Tn * NEXP];      // [B,T,16]     3 MB
__device__ float g_agg[(size_t)Bn * Tn * En];        // [B,T,E]     48 MB
__device__ float g_th [(size_t)Bn * Tn * THn];       // [B,T,TH]    24 MB

// ---------------------------------------------------------------------------
// gin[b,t,:] = inputs[b,t+1,:] + inputs[b,0,:]
// ---------------------------------------------------------------------------
__global__ void gin_kernel(const float* __restrict__ in) {
    int idx = blockIdx.x * blockDim.x + threadIdx.x;
    int total = Bn * Tn * Dn / 4;
    if (idx >= total) return;
    int d4 = idx % (Dn / 4);
    int bt = idx / (Dn / 4);
    int t  = bt % Tn;
    int b  = bt / Tn;
    const float4* base = (const float4*)(in + (size_t)b * Gn * Dn);
    float4 a = base[(size_t)(t + 1) * (Dn / 4) + d4];
    float4 s = base[d4];
    ((float4*)g_gin)[idx] = make_float4(a.x + s.x, a.y + s.y, a.z + s.z, a.w + s.w);
}

// ===========================================================================
// Tensor-core batched GEMM (bf16 3-term split emulating fp32).
// C = A[M,K] @ Bw[K,N] + bias, optional relu.
// Requires: M % 128 == 0, N % 128 == 0, K % 32 == 0  (true for all call sites)
// Block: 128x128x32, 256 threads, 8 warps (4 M x 2 N), warp tile 32x64.
// ===========================================================================
#define PAD 40                     // smem row pitch in bf16 elems (conflict-free)
#define SA  (128 * PAD)            // elems per tile
#define TC_SMEM (2 * 4 * SA * 2)   // 2 stages * 4 tiles * SA elems * 2 bytes = 81920

__device__ __forceinline__ void mma_bf16(float* c,
        unsigned a0, unsigned a1, unsigned a2, unsigned a3,
        unsigned b0, unsigned b1) {
    asm volatile(
        "mma.sync.aligned.m16n8k16.row.col.f32.bf16.bf16.f32 "
        "{%0,%1,%2,%3},{%4,%5,%6,%7},{%8,%9},{%0,%1,%2,%3};"
        : "+f"(c[0]), "+f"(c[1]), "+f"(c[2]), "+f"(c[3])
        : "r"(a0), "r"(a1), "r"(a2), "r"(a3), "r"(b0), "r"(b1));
}

__device__ __forceinline__ unsigned lds32(const __nv_bfloat16* p, int r, int c) {
    return *(const unsigned*)(p + r * PAD + c);
}

__device__ __forceinline__ void split1(float x, __nv_bfloat16& h, __nv_bfloat16& l) {
    h = __float2bfloat16_rn(x);
    l = __float2bfloat16_rn(x - __bfloat162float(h));
}

__global__ void __launch_bounds__(256)
tc_gemm(const float* __restrict__ A, const float* __restrict__ Bw,
        const float* __restrict__ bias, float* __restrict__ C,
        int N, int K, int lda, int ldb, int ldc,
        long aStride, int aDiv, long bStride, long biasStride, long cStride,
        int relu)
{
    extern __shared__ __nv_bfloat16 sm[];
    int z = blockIdx.z;
    A    += (long)(z / aDiv) * aStride;
    Bw   += (long)z * bStride;
    bias += (long)z * biasStride;
    C    += (long)z * cStride;

    int tid  = threadIdx.x;
    int lane = tid & 31, warp = tid >> 5;
    int row0 = blockIdx.x * 128, col0 = blockIdx.y * 128;
    int wm = (warp >> 1) * 32, wn = (warp & 1) * 64;
    int g = lane >> 2, t = lane & 3;

    // gmem load mapping
    int aRow = tid >> 3;            // 0..31 (4 passes of 32 rows)
    int aK   = (tid & 7) * 4;       // float4 along K
    int bK   = tid >> 5;            // 0..7  (4 passes of 8 k-rows)
    int bN   = (tid & 31) * 4;      // float4 along N

    float acc[2][8][4];
    #pragma unroll
    for (int i = 0; i < 2; i++)
        #pragma unroll
        for (int j = 0; j < 8; j++)
            #pragma unroll
            for (int k = 0; k < 4; k++) acc[i][j][k] = 0.0f;

    float4 ra[4], rb[4];
    int nIter = K / 32;

    // prefetch tile 0
    #pragma unroll
    for (int i = 0; i < 4; i++) {
        ra[i] = *(const float4*)&A[(long)(row0 + aRow + 32 * i) * lda + aK];
        rb[i] = *(const float4*)&Bw[(long)(bK + 8 * i) * ldb + col0 + bN];
    }

    // store tile 0 into buffer 0
    {
        __nv_bfloat16 *ah = sm, *al = sm + SA, *bh = sm + 2 * SA, *bl = sm + 3 * SA;
        #pragma unroll
        for (int i = 0; i < 4; i++) {
            int r = aRow + 32 * i;
            float vx[4] = {ra[i].x, ra[i].y, ra[i].z, ra[i].w};
            #pragma unroll
            for (int e = 0; e < 4; e++) {
                __nv_bfloat16 h, l; split1(vx[e], h, l);
                ah[r * PAD + aK + e] = h; al[r * PAD + aK + e] = l;
            }
            int kk = bK + 8 * i;
            float wx[4] = {rb[i].x, rb[i].y, rb[i].z, rb[i].w};
            #pragma unroll
            for (int e = 0; e < 4; e++) {
                __nv_bfloat16 h, l; split1(wx[e], h, l);
                bh[(bN + e) * PAD + kk] = h; bl[(bN + e) * PAD + kk] = l;
            }
        }
    }
    __syncthreads();

    int buf = 0;
    for (int it = 0; it < nIter; it++) {
        // prefetch next tile to regs
        if (it + 1 < nIter) {
            int k0 = (it + 1) * 32;
            #pragma unroll
            for (int i = 0; i < 4; i++) {
                ra[i] = *(const float4*)&A[(long)(row0 + aRow + 32 * i) * lda + k0 + aK];
                rb[i] = *(const float4*)&Bw[(long)(k0 + bK + 8 * i) * ldb + col0 + bN];
            }
        }

        // compute from current buffer
        const __nv_bfloat16* ah = sm + buf * 4 * SA;
        const __nv_bfloat16* al = ah + SA;
        const __nv_bfloat16* bh = ah + 2 * SA;
        const __nv_bfloat16* bl = ah + 3 * SA;

        #pragma unroll
        for (int ks = 0; ks < 32; ks += 16) {
            unsigned Ah[2][4], Al[2][4], Bf[8][2];
            int c = ks + 2 * t;
            #pragma unroll
            for (int mt = 0; mt < 2; mt++) {
                int r = wm + mt * 16 + g;
                Ah[mt][0] = lds32(ah, r,     c);
                Ah[mt][1] = lds32(ah, r + 8, c);
                Ah[mt][2] = lds32(ah, r,     c + 8);
                Ah[mt][3] = lds32(ah, r + 8, c + 8);
                Al[mt][0] = lds32(al, r,     c);
                Al[mt][1] = lds32(al, r + 8, c);
                Al[mt][2] = lds32(al, r,     c + 8);
                Al[mt][3] = lds32(al, r + 8, c + 8);
            }
            #pragma unroll
            for (int nt = 0; nt < 8; nt++) {
                int cc = wn + nt * 8 + g;
                Bf[nt][0] = lds32(bh, cc, c);
                Bf[nt][1] = lds32(bh, cc, c + 8);
            }
            #pragma unroll
            for (int mt = 0; mt < 2; mt++)
                #pragma unroll
                for (int nt = 0; nt < 8; nt++)
                    mma_bf16(acc[mt][nt], Ah[mt][0], Ah[mt][1], Ah[mt][2], Ah[mt][3],
                             Bf[nt][0], Bf[nt][1]);
            #pragma unroll
            for (int mt = 0; mt < 2; mt++)
                #pragma unroll
                for (int nt = 0; nt < 8; nt++)
                    mma_bf16(acc[mt][nt], Al[mt][0], Al[mt][1], Al[mt][2], Al[mt][3],
                             Bf[nt][0], Bf[nt][1]);
            #pragma unroll
            for (int nt = 0; nt < 8; nt++) {
                int cc = wn + nt * 8 + g;
                Bf[nt][0] = lds32(bl, cc, c);
                Bf[nt][1] = lds32(bl, cc, c + 8);
            }
            #pragma unroll
            for (int mt = 0; mt < 2; mt++)
                #pragma unroll
                for (int nt = 0; nt < 8; nt++)
                    mma_bf16(acc[mt][nt], Ah[mt][0], Ah[mt][1], Ah[mt][2], Ah[mt][3],
                             Bf[nt][0], Bf[nt][1]);
        }

        // store prefetched tile into other buffer
        if (it + 1 < nIter) {
            __nv_bfloat16* nah = sm + (buf ^ 1) * 4 * SA;
            __nv_bfloat16* nal = nah + SA;
            __nv_bfloat16* nbh = nah + 2 * SA;
            __nv_bfloat16* nbl = nah + 3 * SA;
            #pragma unroll
            for (int i = 0; i < 4; i++) {
                int r = aRow + 32 * i;
                float vx[4] = {ra[i].x, ra[i].y, ra[i].z, ra[i].w};
                #pragma unroll
                for (int e = 0; e < 4; e++) {
                    __nv_bfloat16 h, l; split1(vx[e], h, l);
                    nah[r * PAD + aK + e] = h; nal[r * PAD + aK + e] = l;
                }
                int kk = bK + 8 * i;
                float wx[4] = {rb[i].x, rb[i].y, rb[i].z, rb[i].w};
                #pragma unroll
                for (int e = 0; e < 4; e++) {
                    __nv_bfloat16 h, l; split1(wx[e], h, l);
                    nbh[(bN + e) * PAD + kk] = h; nbl[(bN + e) * PAD + kk] = l;
                }
            }
        }
        __syncthreads();
        buf ^= 1;
    }

    // epilogue: bias + relu, float2 stores
    #pragma unroll
    for (int mt = 0; mt < 2; mt++) {
        #pragma unroll
        for (int nt = 0; nt < 8; nt++) {
            int col = col0 + wn + nt * 8 + 2 * t;
            long r0 = row0 + wm + mt * 16 + g;
            float b0v = bias[col], b1v = bias[col + 1];
            float2 v0 = make_float2(acc[mt][nt][0] + b0v, acc[mt][nt][1] + b1v);
            float2 v1 = make_float2(acc[mt][nt][2] + b0v, acc[mt][nt][3] + b1v);
            if (relu) {
                v0.x = fmaxf(v0.x, 0.f); v0.y = fmaxf(v0.y, 0.f);
                v1.x = fmaxf(v1.x, 0.f); v1.y = fmaxf(v1.y, 0.f);
            }
            *(float2*)&C[r0 * ldc + col] = v0;
            *(float2*)&C[(r0 + 8) * ldc + col] = v1;
        }
    }
}

// ---------------------------------------------------------------------------
// Scalar FFMA SGEMM for the small tower layers (N=128 / N=64).
// ---------------------------------------------------------------------------
#define BM 128
#define BN 128
#define BK 8
#define TM 8
#define TN 8

__global__ __launch_bounds__(256)
void sgemm_bias(const float* __restrict__ A, const float* __restrict__ Bw,
                const float* __restrict__ bias, float* __restrict__ C,
                int N, int K, int lda, int ldb, int ldc,
                long aStride, int aDiv, long bStride, long biasStride, long cStride,
                int relu)
{
    int z = blockIdx.z;
    A    += (long)(z / aDiv) * aStride;
    Bw   += (long)z * bStride;
    bias += (long)z * biasStride;
    C    += (long)z * cStride;

    __shared__ float As[BK][BM];
    __shared__ float Bs[BK][BN];

    int tid  = threadIdx.x;
    int row0 = blockIdx.x * BM;
    int col0 = blockIdx.y * BN;
    int tx = tid % 16;
    int ty = tid / 16;

    int aRow = tid >> 1;
    int aCol = (tid & 1) * 4;
    int bRow = tid >> 5;
    int bCol = (tid & 31) * 4;
    bool bOk = (col0 + bCol) < N;

    float acc[TM][TN];
    #pragma unroll
    for (int i = 0; i < TM; i++)
        #pragma unroll
        for (int j = 0; j < TN; j++) acc[i][j] = 0.0f;

    for (int k0 = 0; k0 < K; k0 += BK) {
        float4 av = *(const float4*)&A[(long)(row0 + aRow) * lda + k0 + aCol];
        As[aCol + 0][aRow] = av.x;
        As[aCol + 1][aRow] = av.y;
        As[aCol + 2][aRow] = av.z;
        As[aCol + 3][aRow] = av.w;
        if (bOk) {
            float4 bv = *(const float4*)&Bw[(long)(k0 + bRow) * ldb + col0 + bCol];
            *(float4*)&Bs[bRow][bCol] = bv;
        }
        __syncthreads();

        #pragma unroll
        for (int kk = 0; kk < BK; kk++) {
            float4 a0 = *(const float4*)&As[kk][ty * TM];
            float4 a1 = *(const float4*)&As[kk][ty * TM + 4];
            float4 b0 = *(const float4*)&Bs[kk][tx * TN];
            float4 b1 = *(const float4*)&Bs[kk][tx * TN + 4];
            float ra[TM] = {a0.x, a0.y, a0.z, a0.w, a1.x, a1.y, a1.z, a1.w};
            float rb[TN] = {b0.x, b0.y, b0.z, b0.w, b1.x, b1.y, b1.z, b1.w};
            #pragma unroll
            for (int i = 0; i < TM; i++)
                #pragma unroll
                for (int j = 0; j < TN; j++)
                    acc[i][j] += ra[i] * rb[j];
        }
        __syncthreads();
    }

    #pragma unroll
    for (int i = 0; i < TM; i++) {
        long r = row0 + ty * TM + i;
        #pragma unroll
        for (int j0 = 0; j0 < TN; j0 += 4) {
            int c = col0 + tx * TN + j0;
            if (c < N) {
                float4 v;
                v.x = acc[i][j0 + 0] + bias[c + 0];
                v.y = acc[i][j0 + 1] + bias[c + 1];
                v.z = acc[i][j0 + 2] + bias[c + 2];
                v.w = acc[i][j0 + 3] + bias[c + 3];
                if (relu) {
                    v.x = fmaxf(v.x, 0.f); v.y = fmaxf(v.y, 0.f);
                    v.z = fmaxf(v.z, 0.f); v.w = fmaxf(v.w, 0.f);
                }
                *(float4*)&C[r * ldc + c] = v;
            }
        }
    }
}

// ---------------------------------------------------------------------------
// Gate layer 2 + softmax
// ---------------------------------------------------------------------------
__global__ void gate2_softmax_kernel(const float* __restrict__ W2,
                                     const float* __restrict__ b2) {
    int t = blockIdx.y;
    __shared__ float sW[GHn * NEXP];
    __shared__ float sb[NEXP];
    for (int i = threadIdx.x; i < GHn * NEXP; i += blockDim.x)
        sW[i] = W2[(size_t)t * GHn * NEXP + i];
    if (threadIdx.x < NEXP) sb[threadIdx.x] = b2[t * NEXP + threadIdx.x];
    __syncthreads();

    int b = blockIdx.x * blockDim.x + threadIdx.x;
    if (b >= Bn) return;

    const float4* gr = (const float4*)(g_gh + ((size_t)b * Tn + t) * GHn);
    float acc[NEXP];
    #pragma unroll
    for (int k = 0; k < NEXP; k++) acc[k] = sb[k];
    for (int h4 = 0; h4 < GHn / 4; h4++) {
        float4 x = gr[h4];
        const float* w = sW + h4 * 4 * NEXP;
        #pragma unroll
        for (int k = 0; k < NEXP; k++)
            acc[k] += x.x * w[k] + x.y * w[NEXP + k]
                    + x.z * w[2 * NEXP + k] + x.w * w[3 * NEXP + k];
    }
    float mx = acc[0];
    #pragma unroll
    for (int k = 1; k < NEXP; k++) mx = fmaxf(mx, acc[k]);
    float sum = 0.f;
    #pragma unroll
    for (int k = 0; k < NEXP; k++) { acc[k] = expf(acc[k] - mx); sum += acc[k]; }
    float inv = 1.0f / sum;
    float* o = g_gw + ((size_t)b * Tn + t) * NEXP;
    #pragma unroll
    for (int k = 0; k < NEXP; k++) o[k] = acc[k] * inv;
}

// ---------------------------------------------------------------------------
// agg[b,t,:] = sum_k gw[b,t,k] * emb[b,k,:]
// ---------------------------------------------------------------------------
__global__ void agg_kernel() {
    int b = blockIdx.x;
    int e = threadIdx.x;
    __shared__ float sgw[Tn * NEXP];
    if (threadIdx.x < Tn * NEXP)
        sgw[threadIdx.x] = g_gw[(size_t)b * Tn * NEXP + threadIdx.x];
    __syncthreads();
    const float* eb = g_emb + (size_t)b * NEXP * En + e;
    float a0 = 0.f, a1 = 0.f, a2 = 0.f;
    #pragma unroll
    for (int k = 0; k < NEXP; k++) {
        float v = eb[(size_t)k * En];
        a0 += sgw[k] * v;
        a1 += sgw[NEXP + k] * v;
        a2 += sgw[2 * NEXP + k] * v;
    }
    float* o = g_agg + (size_t)b * Tn * En + e;
    o[0]      = a0;
    o[En]     = a1;
    o[2 * En] = a2;
}

// ---------------------------------------------------------------------------
extern "C" void kernel_launch(void* const* d_in, const int* in_sizes, int n_in,
                              void* d_out, int out_size) {
    const float* inputs = (const float*)d_in[0];
    const float* eW1 = (const float*)d_in[1];
    const float* eb1 = (const float*)d_in[2];
    const float* eW2 = (const float*)d_in[3];
    const float* eb2 = (const float*)d_in[4];
    const float* gW1 = (const float*)d_in[5];
    const float* gb1 = (const float*)d_in[6];
    const float* gW2 = (const float*)d_in[7];
    const float* gb2 = (const float*)d_in[8];
    const float* tW1 = (const float*)d_in[9];
    const float* tb1 = (const float*)d_in[10];
    const float* tW2 = (const float*)d_in[11];
    const float* tb2 = (const float*)d_in[12];
    float* out = (float*)d_out;

    float *p_gin, *p_h1, *p_emb, *p_gh, *p_agg, *p_th;
    cudaGetSymbolAddress((void**)&p_gin, g_gin);
    cudaGetSymbolAddress((void**)&p_h1,  g_h1);
    cudaGetSymbolAddress((void**)&p_emb, g_emb);
    cudaGetSymbolAddress((void**)&p_gh,  g_gh);
    cudaGetSymbolAddress((void**)&p_agg, g_agg);
    cudaGetSymbolAddress((void**)&p_th,  g_th);

    cudaFuncSetAttribute(tc_gemm, cudaFuncAttributeMaxDynamicSharedMemorySize, TC_SMEM);

    // gate input = task input + shared input
    gin_kernel<<<(Bn * Tn * Dn / 4 + 255) / 256, 256>>>(inputs);

    // expert layer 1 (tensor cores)
    tc_gemm<<<dim3(Bn / 128, Hn / 128, NEXP), 256, TC_SMEM>>>(
        inputs, eW1, eb1, p_h1,
        Hn, Dn, Gn * Dn, Hn, NEXP * Hn,
        (long)Dn, NEn, (long)Dn * Hn, (long)Hn, (long)Hn, 1);

    // expert layer 2 (tensor cores)
    tc_gemm<<<dim3(Bn / 128, En / 128, NEXP), 256, TC_SMEM>>>(
        p_h1, eW2, eb2, p_emb,
        En, Hn, NEXP * Hn, En, NEXP * En,
        (long)Hn, 1, (long)Hn * En, (long)En, (long)En, 0);

    // gate layer 1 (tensor cores)
    tc_gemm<<<dim3(Bn / 128, GHn / 128, Tn), 256, TC_SMEM>>>(
        p_gin, gW1, gb1, p_gh,
        GHn, Dn, Tn * Dn, GHn, Tn * GHn,
        (long)Dn, 1, (long)Dn * GHn, (long)GHn, (long)GHn, 1);

    // gate layer 2 + softmax
    gate2_softmax_kernel<<<dim3(Bn / 256, Tn), 256>>>(gW2, gb2);

    // weighted expert aggregation
    agg_kernel<<<Bn, En>>>();

    // tower layer 1
    sgemm_bias<<<dim3(Bn / BM, 1, Tn), 256>>>(
        p_agg, tW1, tb1, p_th,
        THn, En, Tn * En, THn, Tn * THn,
        (long)En, 1, (long)En * THn, (long)THn, (long)THn, 1);

    // tower layer 2 -> final output [B, T*TO]
    sgemm_bias<<<dim3(Bn / BM, 1, Tn), 256>>>(
        p_th, tW2, tb2, out,
        TOn, THn, Tn * THn, TOn, Tn * TOn,
        (long)THn, 1, (long)THn * TOn, (long)TOn, (long)TOn, 0);
}

// round 4
// speedup vs baseline: 1.3702x; 1.3106x over previous
#include <cuda_runtime.h>
#include <cuda_bf16.h>
#include <cstdint>
#include <math.h>

// Problem dims
#define Bn   16384
#define Tn   3
#define Dn   512
#define Gn   4
#define NEn  4
#define NEXP 16      // G * NE
#define Hn   512
#define En   256
#define GHn  256
#define THn  128
#define TOn  64

// Scratch (static device globals -- allocation-free per harness rules)
__device__ float g_gin[(size_t)Bn * Tn * Dn];
__device__ float g_h1 [(size_t)Bn * NEXP * Hn];
__device__ float g_emb[(size_t)Bn * NEXP * En];
__device__ float g_gh [(size_t)Bn * Tn * GHn];
__device__ float g_gw [(size_t)Bn * Tn * NEXP];
__device__ float g_agg[(size_t)Bn * Tn * En];
__device__ float g_th [(size_t)Bn * Tn * THn];

// ---------------------------------------------------------------------------
__global__ void gin_kernel(const float* __restrict__ in) {
    int idx = blockIdx.x * blockDim.x + threadIdx.x;
    int total = Bn * Tn * Dn / 4;
    if (idx >= total) return;
    int d4 = idx % (Dn / 4);
    int bt = idx / (Dn / 4);
    int t  = bt % Tn;
    int b  = bt / Tn;
    const float4* base = (const float4*)(in + (size_t)b * Gn * Dn);
    float4 a = base[(size_t)(t + 1) * (Dn / 4) + d4];
    float4 s = base[d4];
    ((float4*)g_gin)[idx] = make_float4(a.x + s.x, a.y + s.y, a.z + s.z, a.w + s.w);
}

// ===========================================================================
// Tensor-core batched GEMM, bf16 3-term split, ldmatrix fragment loads.
// Block tile 128x64x32, 256 threads (8 warps: 4M x 2N), warp tile 32x32.
// 2 CTAs/SM (regs capped at 128, smem 58KB/CTA).
// ===========================================================================
#define APITCH 40   // A smem pitch (bf16): 80B row stride, ldmatrix conflict-free
#define BPITCH 72   // B smem pitch (bf16): 144B row stride, conflict-free
#define AH_OFF 0
#define AL_OFF (128 * APITCH)              // 5120
#define BH_OFF (2 * 128 * APITCH)          // 10240
#define BL_OFF (2 * 128 * APITCH + 32 * BPITCH)  // 12544
#define BUF_ELEMS (2 * 128 * APITCH + 2 * 32 * BPITCH)  // 14848 elems
#define TC_SMEM (2 * BUF_ELEMS * 2)        // 59392 bytes

__device__ __forceinline__ void mma_bf16(float* c,
        const unsigned* a, const unsigned* b) {
    asm volatile(
        "mma.sync.aligned.m16n8k16.row.col.f32.bf16.bf16.f32 "
        "{%0,%1,%2,%3},{%4,%5,%6,%7},{%8,%9},{%0,%1,%2,%3};"
        : "+f"(c[0]), "+f"(c[1]), "+f"(c[2]), "+f"(c[3])
        : "r"(a[0]), "r"(a[1]), "r"(a[2]), "r"(a[3]), "r"(b[0]), "r"(b[1]));
}

__device__ __forceinline__ void ldsm4(unsigned& r0, unsigned& r1,
                                      unsigned& r2, unsigned& r3, unsigned addr) {
    asm volatile("ldmatrix.sync.aligned.m8n8.x4.shared.b16 {%0,%1,%2,%3},[%4];"
                 : "=r"(r0), "=r"(r1), "=r"(r2), "=r"(r3) : "r"(addr));
}

__device__ __forceinline__ void ldsm4t(unsigned& r0, unsigned& r1,
                                       unsigned& r2, unsigned& r3, unsigned addr) {
    asm volatile("ldmatrix.sync.aligned.m8n8.x4.trans.shared.b16 {%0,%1,%2,%3},[%4];"
                 : "=r"(r0), "=r"(r1), "=r"(r2), "=r"(r3) : "r"(addr));
}

// split float -> (hi bf16, lo bf16)
__device__ __forceinline__ void split1(float x, unsigned short& h, unsigned short& l) {
    __nv_bfloat16 hb = __float2bfloat16_rn(x);
    __nv_bfloat16 lb = __float2bfloat16_rn(x - __bfloat162float(hb));
    h = __bfloat16_as_ushort(hb);
    l = __bfloat16_as_ushort(lb);
}

__device__ __forceinline__ void split4(float4 v, uint2& hi, uint2& lo) {
    unsigned short h0, l0, h1, l1, h2, l2, h3, l3;
    split1(v.x, h0, l0); split1(v.y, h1, l1);
    split1(v.z, h2, l2); split1(v.w, h3, l3);
    hi.x = (unsigned)h0 | ((unsigned)h1 << 16);
    hi.y = (unsigned)h2 | ((unsigned)h3 << 16);
    lo.x = (unsigned)l0 | ((unsigned)l1 << 16);
    lo.y = (unsigned)l2 | ((unsigned)l3 << 16);
}

__global__ void __launch_bounds__(256, 2)
tc_gemm(const float* __restrict__ A, const float* __restrict__ Bw,
        const float* __restrict__ bias, float* __restrict__ C,
        int N, int K, int lda, int ldb, int ldc,
        long aStride, int aDiv, long bStride, long biasStride, long cStride,
        int relu)
{
    extern __shared__ __nv_bfloat16 sm[];
    int z = blockIdx.z;
    A    += (long)(z / aDiv) * aStride;
    Bw   += (long)z * bStride;
    bias += (long)z * biasStride;
    C    += (long)z * cStride;

    int tid  = threadIdx.x;
    int lane = tid & 31, warp = tid >> 5;
    int row0 = blockIdx.x * 128, col0 = blockIdx.y * 64;
    int wm = (warp >> 1) * 32, wn = (warp & 1) * 32;
    int g = lane >> 2, qt = lane & 3;

    unsigned sbase = (unsigned)__cvta_generic_to_shared(sm);

    // ldmatrix per-lane row/col offsets
    int rA = (lane & 7) + ((lane >> 3) & 1) * 8;   // A row within 16
    int cA = ((lane >> 4) & 1) * 8;                // A k-chunk
    int rB = (lane & 7) + ((lane >> 3) & 1) * 8;   // B k-row within 16
    int cB = ((lane >> 4) & 1) * 8;                // B n-chunk

    // gmem load mapping
    int aRow = tid >> 2;            // 0..63 (+64)
    int aK   = (tid & 3) * 4;       // 0,4,8,12 (+16)
    int bK   = tid >> 3;            // 0..31
    int bN   = (tid & 7) * 4;       // 0..28 (+32)

    float acc[2][4][4];
    #pragma unroll
    for (int i = 0; i < 2; i++)
        #pragma unroll
        for (int j = 0; j < 4; j++)
            #pragma unroll
            for (int k = 0; k < 4; k++) acc[i][j][k] = 0.0f;

    float4 ra[4], rb[2];
    int nIter = K / 32;

    // prefetch tile 0
    #pragma unroll
    for (int i = 0; i < 4; i++)
        ra[i] = *(const float4*)&A[(long)(row0 + aRow + (i >> 1) * 64) * lda + aK + (i & 1) * 16];
    #pragma unroll
    for (int i = 0; i < 2; i++)
        rb[i] = *(const float4*)&Bw[(long)bK * ldb + col0 + bN + i * 32];

    // store tile 0
    {
        __nv_bfloat16* bp = sm;
        #pragma unroll
        for (int i = 0; i < 4; i++) {
            int r = aRow + (i >> 1) * 64, k = aK + (i & 1) * 16;
            uint2 hi, lo; split4(ra[i], hi, lo);
            *(uint2*)(bp + AH_OFF + r * APITCH + k) = hi;
            *(uint2*)(bp + AL_OFF + r * APITCH + k) = lo;
        }
        #pragma unroll
        for (int i = 0; i < 2; i++) {
            int n = bN + i * 32;
            uint2 hi, lo; split4(rb[i], hi, lo);
            *(uint2*)(bp + BH_OFF + bK * BPITCH + n) = hi;
            *(uint2*)(bp + BL_OFF + bK * BPITCH + n) = lo;
        }
    }
    __syncthreads();

    int buf = 0;
    for (int it = 0; it < nIter; it++) {
        if (it + 1 < nIter) {
            int k0 = (it + 1) * 32;
            #pragma unroll
            for (int i = 0; i < 4; i++)
                ra[i] = *(const float4*)&A[(long)(row0 + aRow + (i >> 1) * 64) * lda + k0 + aK + (i & 1) * 16];
            #pragma unroll
            for (int i = 0; i < 2; i++)
                rb[i] = *(const float4*)&Bw[(long)(k0 + bK) * ldb + col0 + bN + i * 32];
        }

        unsigned bufb = sbase + buf * (BUF_ELEMS * 2);

        #pragma unroll
        for (int ks = 0; ks < 32; ks += 16) {
            unsigned Ah[2][4], Al[2][4], Bh[4][2], Bl[4][2];
            #pragma unroll
            for (int mt = 0; mt < 2; mt++) {
                unsigned ad = bufb + (AH_OFF + (wm + mt * 16 + rA) * APITCH + ks + cA) * 2;
                ldsm4(Ah[mt][0], Ah[mt][1], Ah[mt][2], Ah[mt][3], ad);
                ldsm4(Al[mt][0], Al[mt][1], Al[mt][2], Al[mt][3], ad + (AL_OFF - AH_OFF) * 2);
            }
            #pragma unroll
            for (int np = 0; np < 2; np++) {
                unsigned bd = bufb + (BH_OFF + (ks + rB) * BPITCH + wn + np * 16 + cB) * 2;
                ldsm4t(Bh[2*np][0], Bh[2*np][1], Bh[2*np+1][0], Bh[2*np+1][1], bd);
                ldsm4t(Bl[2*np][0], Bl[2*np][1], Bl[2*np+1][0], Bl[2*np+1][1],
                       bd + (BL_OFF - BH_OFF) * 2);
            }
            #pragma unroll
            for (int mt = 0; mt < 2; mt++)
                #pragma unroll
                for (int nt = 0; nt < 4; nt++)
                    mma_bf16(acc[mt][nt], Ah[mt], Bh[nt]);
            #pragma unroll
            for (int mt = 0; mt < 2; mt++)
                #pragma unroll
                for (int nt = 0; nt < 4; nt++)
                    mma_bf16(acc[mt][nt], Al[mt], Bh[nt]);
            #pragma unroll
            for (int mt = 0; mt < 2; mt++)
                #pragma unroll
                for (int nt = 0; nt < 4; nt++)
                    mma_bf16(acc[mt][nt], Ah[mt], Bl[nt]);
        }

        if (it + 1 < nIter) {
            __nv_bfloat16* bp = sm + (buf ^ 1) * BUF_ELEMS;
            #pragma unroll
            for (int i = 0; i < 4; i++) {
                int r = aRow + (i >> 1) * 64, k = aK + (i & 1) * 16;
                uint2 hi, lo; split4(ra[i], hi, lo);
                *(uint2*)(bp + AH_OFF + r * APITCH + k) = hi;
                *(uint2*)(bp + AL_OFF + r * APITCH + k) = lo;
            }
            #pragma unroll
            for (int i = 0; i < 2; i++) {
                int n = bN + i * 32;
                uint2 hi, lo; split4(rb[i], hi, lo);
                *(uint2*)(bp + BH_OFF + bK * BPITCH + n) = hi;
                *(uint2*)(bp + BL_OFF + bK * BPITCH + n) = lo;
            }
        }
        __syncthreads();
        buf ^= 1;
    }

    // epilogue
    #pragma unroll
    for (int mt = 0; mt < 2; mt++) {
        #pragma unroll
        for (int nt = 0; nt < 4; nt++) {
            int col = col0 + wn + nt * 8 + 2 * qt;
            long r0 = row0 + wm + mt * 16 + g;
            float b0v = bias[col], b1v = bias[col + 1];
            float2 v0 = make_float2(acc[mt][nt][0] + b0v, acc[mt][nt][1] + b1v);
            float2 v1 = make_float2(acc[mt][nt][2] + b0v, acc[mt][nt][3] + b1v);
            if (relu) {
                v0.x = fmaxf(v0.x, 0.f); v0.y = fmaxf(v0.y, 0.f);
                v1.x = fmaxf(v1.x, 0.f); v1.y = fmaxf(v1.y, 0.f);
            }
            *(float2*)&C[r0 * ldc + col] = v0;
            *(float2*)&C[(r0 + 8) * ldc + col] = v1;
        }
    }
}

// ---------------------------------------------------------------------------
// Scalar FFMA SGEMM for the small tower layers.
// ---------------------------------------------------------------------------
#define BM 128
#define BN 128
#define BK 8
#define TM 8
#define TN 8

__global__ __launch_bounds__(256)
void sgemm_bias(const float* __restrict__ A, const float* __restrict__ Bw,
                const float* __restrict__ bias, float* __restrict__ C,
                int N, int K, int lda, int ldb, int ldc,
                long aStride, int aDiv, long bStride, long biasStride, long cStride,
                int relu)
{
    int z = blockIdx.z;
    A    += (long)(z / aDiv) * aStride;
    Bw   += (long)z * bStride;
    bias += (long)z * biasStride;
    C    += (long)z * cStride;

    __shared__ float As[BK][BM];
    __shared__ float Bs[BK][BN];

    int tid  = threadIdx.x;
    int row0 = blockIdx.x * BM;
    int col0 = blockIdx.y * BN;
    int tx = tid % 16;
    int ty = tid / 16;

    int aRow = tid >> 1;
    int aCol = (tid & 1) * 4;
    int bRow = tid >> 5;
    int bCol = (tid & 31) * 4;
    bool bOk = (col0 + bCol) < N;

    float acc[TM][TN];
    #pragma unroll
    for (int i = 0; i < TM; i++)
        #pragma unroll
        for (int j = 0; j < TN; j++) acc[i][j] = 0.0f;

    for (int k0 = 0; k0 < K; k0 += BK) {
        float4 av = *(const float4*)&A[(long)(row0 + aRow) * lda + k0 + aCol];
        As[aCol + 0][aRow] = av.x;
        As[aCol + 1][aRow] = av.y;
        As[aCol + 2][aRow] = av.z;
        As[aCol + 3][aRow] = av.w;
        if (bOk) {
            float4 bv = *(const float4*)&Bw[(long)(k0 + bRow) * ldb + col0 + bCol];
            *(float4*)&Bs[bRow][bCol] = bv;
        }
        __syncthreads();

        #pragma unroll
        for (int kk = 0; kk < BK; kk++) {
            float4 a0 = *(const float4*)&As[kk][ty * TM];
            float4 a1 = *(const float4*)&As[kk][ty * TM + 4];
            float4 b0 = *(const float4*)&Bs[kk][tx * TN];
            float4 b1 = *(const float4*)&Bs[kk][tx * TN + 4];
            float ra[TM] = {a0.x, a0.y, a0.z, a0.w, a1.x, a1.y, a1.z, a1.w};
            float rbv[TN] = {b0.x, b0.y, b0.z, b0.w, b1.x, b1.y, b1.z, b1.w};
            #pragma unroll
            for (int i = 0; i < TM; i++)
                #pragma unroll
                for (int j = 0; j < TN; j++)
                    acc[i][j] += ra[i] * rbv[j];
        }
        __syncthreads();
    }

    #pragma unroll
    for (int i = 0; i < TM; i++) {
        long r = row0 + ty * TM + i;
        #pragma unroll
        for (int j0 = 0; j0 < TN; j0 += 4) {
            int c = col0 + tx * TN + j0;
            if (c < N) {
                float4 v;
                v.x = acc[i][j0 + 0] + bias[c + 0];
                v.y = acc[i][j0 + 1] + bias[c + 1];
                v.z = acc[i][j0 + 2] + bias[c + 2];
                v.w = acc[i][j0 + 3] + bias[c + 3];
                if (relu) {
                    v.x = fmaxf(v.x, 0.f); v.y = fmaxf(v.y, 0.f);
                    v.z = fmaxf(v.z, 0.f); v.w = fmaxf(v.w, 0.f);
                }
                *(float4*)&C[r * ldc + c] = v;
            }
        }
    }
}

// ---------------------------------------------------------------------------
__global__ void gate2_softmax_kernel(const float* __restrict__ W2,
                                     const float* __restrict__ b2) {
    int t = blockIdx.y;
    __shared__ float sW[GHn * NEXP];
    __shared__ float sb[NEXP];
    for (int i = threadIdx.x; i < GHn * NEXP; i += blockDim.x)
        sW[i] = W2[(size_t)t * GHn * NEXP + i];
    if (threadIdx.x < NEXP) sb[threadIdx.x] = b2[t * NEXP + threadIdx.x];
    __syncthreads();

    int b = blockIdx.x * blockDim.x + threadIdx.x;
    if (b >= Bn) return;

    const float4* gr = (const float4*)(g_gh + ((size_t)b * Tn + t) * GHn);
    float acc[NEXP];
    #pragma unroll
    for (int k = 0; k < NEXP; k++) acc[k] = sb[k];
    for (int h4 = 0; h4 < GHn / 4; h4++) {
        float4 x = gr[h4];
        const float* w = sW + h4 * 4 * NEXP;
        #pragma unroll
        for (int k = 0; k < NEXP; k++)
            acc[k] += x.x * w[k] + x.y * w[NEXP + k]
                    + x.z * w[2 * NEXP + k] + x.w * w[3 * NEXP + k];
    }
    float mx = acc[0];
    #pragma unroll
    for (int k = 1; k < NEXP; k++) mx = fmaxf(mx, acc[k]);
    float sum = 0.f;
    #pragma unroll
    for (int k = 0; k < NEXP; k++) { acc[k] = expf(acc[k] - mx); sum += acc[k]; }
    float inv = 1.0f / sum;
    float* o = g_gw + ((size_t)b * Tn + t) * NEXP;
    #pragma unroll
    for (int k = 0; k < NEXP; k++) o[k] = acc[k] * inv;
}

// ---------------------------------------------------------------------------
__global__ void agg_kernel() {
    int b = blockIdx.x;
    int e = threadIdx.x;
    __shared__ float sgw[Tn * NEXP];
    if (threadIdx.x < Tn * NEXP)
        sgw[threadIdx.x] = g_gw[(size_t)b * Tn * NEXP + threadIdx.x];
    __syncthreads();
    const float* eb = g_emb + (size_t)b * NEXP * En + e;
    float a0 = 0.f, a1 = 0.f, a2 = 0.f;
    #pragma unroll
    for (int k = 0; k < NEXP; k++) {
        float v = eb[(size_t)k * En];
        a0 += sgw[k] * v;
        a1 += sgw[NEXP + k] * v;
        a2 += sgw[2 * NEXP + k] * v;
    }
    float* o = g_agg + (size_t)b * Tn * En + e;
    o[0]      = a0;
    o[En]     = a1;
    o[2 * En] = a2;
}

// ---------------------------------------------------------------------------
extern "C" void kernel_launch(void* const* d_in, const int* in_sizes, int n_in,
                              void* d_out, int out_size) {
    const float* inputs = (const float*)d_in[0];
    const float* eW1 = (const float*)d_in[1];
    const float* eb1 = (const float*)d_in[2];
    const float* eW2 = (const float*)d_in[3];
    const float* eb2 = (const float*)d_in[4];
    const float* gW1 = (const float*)d_in[5];
    const float* gb1 = (const float*)d_in[6];
    const float* gW2 = (const float*)d_in[7];
    const float* gb2 = (const float*)d_in[8];
    const float* tW1 = (const float*)d_in[9];
    const float* tb1 = (const float*)d_in[10];
    const float* tW2 = (const float*)d_in[11];
    const float* tb2 = (const float*)d_in[12];
    float* out = (float*)d_out;

    float *p_gin, *p_h1, *p_emb, *p_gh, *p_agg, *p_th;
    cudaGetSymbolAddress((void**)&p_gin, g_gin);
    cudaGetSymbolAddress((void**)&p_h1,  g_h1);
    cudaGetSymbolAddress((void**)&p_emb, g_emb);
    cudaGetSymbolAddress((void**)&p_gh,  g_gh);
    cudaGetSymbolAddress((void**)&p_agg, g_agg);
    cudaGetSymbolAddress((void**)&p_th,  g_th);

    cudaFuncSetAttribute(tc_gemm, cudaFuncAttributeMaxDynamicSharedMemorySize, TC_SMEM);

    gin_kernel<<<(Bn * Tn * Dn / 4 + 255) / 256, 256>>>(inputs);

    // expert layer 1 (tensor cores): N=512
    tc_gemm<<<dim3(Bn / 128, Hn / 64, NEXP), 256, TC_SMEM>>>(
        inputs, eW1, eb1, p_h1,
        Hn, Dn, Gn * Dn, Hn, NEXP * Hn,
        (long)Dn, NEn, (long)Dn * Hn, (long)Hn, (long)Hn, 1);

    // expert layer 2 (tensor cores): N=256
    tc_gemm<<<dim3(Bn / 128, En / 64, NEXP), 256, TC_SMEM>>>(
        p_h1, eW2, eb2, p_emb,
        En, Hn, NEXP * Hn, En, NEXP * En,
        (long)Hn, 1, (long)Hn * En, (long)En, (long)En, 0);

    // gate layer 1 (tensor cores): N=256
    tc_gemm<<<dim3(Bn / 128, GHn / 64, Tn), 256, TC_SMEM>>>(
        p_gin, gW1, gb1, p_gh,
        GHn, Dn, Tn * Dn, GHn, Tn * GHn,
        (long)Dn, 1, (long)Dn * GHn, (long)GHn, (long)GHn, 1);

    gate2_softmax_kernel<<<dim3(Bn / 256, Tn), 256>>>(gW2, gb2);

    agg_kernel<<<Bn, En>>>();

    sgemm_bias<<<dim3(Bn / BM, 1, Tn), 256>>>(
        p_agg, tW1, tb1, p_th,
        THn, En, Tn * En, THn, Tn * THn,
        (long)En, 1, (long)En * THn, (long)THn, (long)THn, 1);

    sgemm_bias<<<dim3(Bn / BM, 1, Tn), 256>>>(
        p_th, tW2, tb2, out,
        TOn, THn, Tn * THn, TOn, Tn * TOn,
        (long)THn, 1, (long)THn * TOn, (long)TOn, (long)TOn, 0);
}

// round 6
// speedup vs baseline: 1.9719x; 1.4391x over previous
#include <cuda_runtime.h>
#include <cuda_bf16.h>
#include <cstdint>
#include <math.h>

// Problem dims
#define Bn   16384
#define Tn   3
#define Dn   512
#define Gn   4
#define NEn  4
#define NEXP 16
#define Hn   512
#define En   256
#define GHn  256
#define THn  128
#define TOn  64

// ---------------- scratch (device globals; no allocs allowed) ----------------
__device__ __nv_bfloat16 s_inh [(size_t)Bn * Gn * Dn];
__device__ __nv_bfloat16 s_inl [(size_t)Bn * Gn * Dn];
__device__ __nv_bfloat16 s_ginh[(size_t)Bn * Tn * Dn];
__device__ __nv_bfloat16 s_ginl[(size_t)Bn * Tn * Dn];
__device__ __nv_bfloat16 s_h1h [(size_t)Bn * NEXP * Hn];
__device__ __nv_bfloat16 s_h1l [(size_t)Bn * NEXP * Hn];
__device__ __nv_bfloat16 s_we1h[(size_t)NEXP * Dn * Hn];   // [e][D][H]  (K-major, same as src)
__device__ __nv_bfloat16 s_we1l[(size_t)NEXP * Dn * Hn];
__device__ __nv_bfloat16 s_we2h[(size_t)NEXP * Hn * En];   // [e][H][E]
__device__ __nv_bfloat16 s_we2l[(size_t)NEXP * Hn * En];
__device__ __nv_bfloat16 s_wg1h[(size_t)Tn * Dn * GHn];    // [t][D][GH]
__device__ __nv_bfloat16 s_wg1l[(size_t)Tn * Dn * GHn];
__device__ float g_emb[(size_t)Bn * NEXP * En];
__device__ float g_gh [(size_t)Bn * Tn * GHn];
__device__ float g_gw [(size_t)Bn * Tn * NEXP];
__device__ float g_agg[(size_t)Bn * Tn * En];
__device__ float g_th [(size_t)Bn * Tn * THn];

// ---------------- helpers ----------------
__device__ __forceinline__ void split1(float x, unsigned short& h, unsigned short& l) {
    __nv_bfloat16 hb = __float2bfloat16_rn(x);
    __nv_bfloat16 lb = __float2bfloat16_rn(x - __bfloat162float(hb));
    h = __bfloat16_as_ushort(hb);
    l = __bfloat16_as_ushort(lb);
}
__device__ __forceinline__ void split4(float4 v, uint2& hi, uint2& lo) {
    unsigned short h0,l0,h1,l1,h2,l2,h3,l3;
    split1(v.x,h0,l0); split1(v.y,h1,l1); split1(v.z,h2,l2); split1(v.w,h3,l3);
    hi.x = (unsigned)h0 | ((unsigned)h1 << 16);
    hi.y = (unsigned)h2 | ((unsigned)h3 << 16);
    lo.x = (unsigned)l0 | ((unsigned)l1 << 16);
    lo.y = (unsigned)l2 | ((unsigned)l3 << 16);
}

// ---------------- conversion kernels ----------------
__global__ void conv_split(const float* __restrict__ in,
                           __nv_bfloat16* __restrict__ h,
                           __nv_bfloat16* __restrict__ l, int n4) {
    int i = blockIdx.x * blockDim.x + threadIdx.x;
    if (i >= n4) return;
    float4 v = ((const float4*)in)[i];
    uint2 hi, lo; split4(v, hi, lo);
    ((uint2*)h)[i] = hi;
    ((uint2*)l)[i] = lo;
}

__global__ void conv_gin(const float* __restrict__ in) {
    int i = blockIdx.x * blockDim.x + threadIdx.x;
    int total = Bn * Tn * Dn / 4;
    if (i >= total) return;
    int d4 = i % (Dn / 4);
    int bt = i / (Dn / 4);
    int t  = bt % Tn;
    int b  = bt / Tn;
    const float4* base = (const float4*)(in + (size_t)b * Gn * Dn);
    float4 a = base[(size_t)(t + 1) * (Dn / 4) + d4];
    float4 s = base[d4];
    float4 v = make_float4(a.x + s.x, a.y + s.y, a.z + s.z, a.w + s.w);
    uint2 hi, lo; split4(v, hi, lo);
    ((uint2*)s_ginh)[i] = hi;
    ((uint2*)s_ginl)[i] = lo;
}

// ===========================================================================
// Tensor-core batched GEMM, pre-split bf16 hi/lo inputs, 3-term split.
// A [M,K] row-major bf16 (hi/lo); B [K,N] row-major bf16 (hi/lo).
// Block tile 128x64x32, 256 threads (8 warps: 4M x 2N), warp tile 32x32.
// Output: fp32 C, or bf16 hi/lo pair (splitOut).
// ===========================================================================
#define APITCH 40
#define BPITCH 72
#define AH_OFF 0
#define AL_OFF (128 * APITCH)                    // 5120
#define BH_OFF (2 * 128 * APITCH)                // 10240
#define BL_OFF (2 * 128 * APITCH + 32 * BPITCH)  // 12544
#define BUF_ELEMS (2 * 128 * APITCH + 2 * 32 * BPITCH)  // 14848
#define TC_SMEM (2 * BUF_ELEMS * 2)              // 59392 bytes

__device__ __forceinline__ void mma_bf16(float* c,
        const unsigned* a, const unsigned* b) {
    asm volatile(
        "mma.sync.aligned.m16n8k16.row.col.f32.bf16.bf16.f32 "
        "{%0,%1,%2,%3},{%4,%5,%6,%7},{%8,%9},{%0,%1,%2,%3};"
        : "+f"(c[0]), "+f"(c[1]), "+f"(c[2]), "+f"(c[3])
        : "r"(a[0]), "r"(a[1]), "r"(a[2]), "r"(a[3]), "r"(b[0]), "r"(b[1]));
}
__device__ __forceinline__ void ldsm4(unsigned& r0, unsigned& r1,
                                      unsigned& r2, unsigned& r3, unsigned addr) {
    asm volatile("ldmatrix.sync.aligned.m8n8.x4.shared.b16 {%0,%1,%2,%3},[%4];"
                 : "=r"(r0), "=r"(r1), "=r"(r2), "=r"(r3) : "r"(addr));
}
__device__ __forceinline__ void ldsm4t(unsigned& r0, unsigned& r1,
                                       unsigned& r2, unsigned& r3, unsigned addr) {
    asm volatile("ldmatrix.sync.aligned.m8n8.x4.trans.shared.b16 {%0,%1,%2,%3},[%4];"
                 : "=r"(r0), "=r"(r1), "=r"(r2), "=r"(r3) : "r"(addr));
}

__global__ void __launch_bounds__(256, 2)
tc_gemm(const __nv_bfloat16* __restrict__ Ah, const __nv_bfloat16* __restrict__ Al,
        const __nv_bfloat16* __restrict__ Bh, const __nv_bfloat16* __restrict__ Bl,
        const float* __restrict__ bias,
        float* __restrict__ C, __nv_bfloat16* __restrict__ Ch, __nv_bfloat16* __restrict__ Cl,
        int K, int lda, int ldb, int ldc,
        long aStride, int aDiv, long bStride, long biasStride, long cStride,
        int relu, int splitOut)
{
    extern __shared__ __nv_bfloat16 sm[];
    int z = blockIdx.z;
    Ah += (long)(z / aDiv) * aStride;  Al += (long)(z / aDiv) * aStride;
    Bh += (long)z * bStride;           Bl += (long)z * bStride;
    bias += (long)z * biasStride;
    if (splitOut) { Ch += (long)z * cStride; Cl += (long)z * cStride; }
    else          { C  += (long)z * cStride; }

    int tid  = threadIdx.x;
    int lane = tid & 31, warp = tid >> 5;
    int row0 = blockIdx.x * 128, col0 = blockIdx.y * 64;
    int wm = (warp >> 1) * 32, wn = (warp & 1) * 32;
    int g = lane >> 2, qt = lane & 3;

    unsigned sbase = (unsigned)__cvta_generic_to_shared(sm);

    // ldmatrix per-lane offsets
    int rA = (lane & 7) + ((lane >> 3) & 1) * 8;
    int cA = ((lane >> 4) & 1) * 8;
    int rB = (lane & 7) + ((lane >> 3) & 1) * 8;
    int cB = ((lane >> 4) & 1) * 8;

    // gmem load mapping
    int aRow = tid >> 1;            // 0..127
    int aK16 = (tid & 1) * 16;      // two uint4 per thread along K
    int bK   = tid >> 3;            // 0..31
    int bN8  = (tid & 7) * 8;       // 8 bf16 per thread along N

    float acc[2][4][4];
    #pragma unroll
    for (int i = 0; i < 2; i++)
        #pragma unroll
        for (int j = 0; j < 4; j++)
            #pragma unroll
            for (int k = 0; k < 4; k++) acc[i][j][k] = 0.0f;

    const __nv_bfloat16* aSrcH = Ah + (long)(row0 + aRow) * lda + aK16;
    const __nv_bfloat16* aSrcL = Al + (long)(row0 + aRow) * lda + aK16;
    const __nv_bfloat16* bSrcH = Bh + (long)bK * ldb + col0 + bN8;
    const __nv_bfloat16* bSrcL = Bl + (long)bK * ldb + col0 + bN8;

    uint4 va0, va1, vl0, vl1, vbh, vbl;
    int nIter = K / 32;

    // prefetch tile 0
    va0 = *(const uint4*)(aSrcH);
    va1 = *(const uint4*)(aSrcH + 8);
    vl0 = *(const uint4*)(aSrcL);
    vl1 = *(const uint4*)(aSrcL + 8);
    vbh = *(const uint4*)(bSrcH);
    vbl = *(const uint4*)(bSrcL);

    // store tile 0
    {
        __nv_bfloat16* bp = sm;
        *(uint4*)(bp + AH_OFF + aRow * APITCH + aK16)     = va0;
        *(uint4*)(bp + AH_OFF + aRow * APITCH + aK16 + 8) = va1;
        *(uint4*)(bp + AL_OFF + aRow * APITCH + aK16)     = vl0;
        *(uint4*)(bp + AL_OFF + aRow * APITCH + aK16 + 8) = vl1;
        *(uint4*)(bp + BH_OFF + bK * BPITCH + bN8) = vbh;
        *(uint4*)(bp + BL_OFF + bK * BPITCH + bN8) = vbl;
    }
    __syncthreads();

    int buf = 0;
    for (int it = 0; it < nIter; it++) {
        if (it + 1 < nIter) {
            int k0 = (it + 1) * 32;
            va0 = *(const uint4*)(aSrcH + k0);
            va1 = *(const uint4*)(aSrcH + k0 + 8);
            vl0 = *(const uint4*)(aSrcL + k0);
            vl1 = *(const uint4*)(aSrcL + k0 + 8);
            vbh = *(const uint4*)(bSrcH + (long)k0 * ldb);
            vbl = *(const uint4*)(bSrcL + (long)k0 * ldb);
        }

        unsigned bufb = sbase + buf * (BUF_ELEMS * 2);

        #pragma unroll
        for (int ks = 0; ks < 32; ks += 16) {
            unsigned Afh[2][4], Afl[2][4], Bfh[4][2], Bfl[4][2];
            #pragma unroll
            for (int mt = 0; mt < 2; mt++) {
                unsigned ad = bufb + (AH_OFF + (wm + mt * 16 + rA) * APITCH + ks + cA) * 2;
                ldsm4(Afh[mt][0], Afh[mt][1], Afh[mt][2], Afh[mt][3], ad);
                ldsm4(Afl[mt][0], Afl[mt][1], Afl[mt][2], Afl[mt][3],
                      ad + (AL_OFF - AH_OFF) * 2);
            }
            #pragma unroll
            for (int np = 0; np < 2; np++) {
                unsigned bd = bufb + (BH_OFF + (ks + rB) * BPITCH + wn + np * 16 + cB) * 2;
                ldsm4t(Bfh[2*np][0], Bfh[2*np][1], Bfh[2*np+1][0], Bfh[2*np+1][1], bd);
                ldsm4t(Bfl[2*np][0], Bfl[2*np][1], Bfl[2*np+1][0], Bfl[2*np+1][1],
                       bd + (BL_OFF - BH_OFF) * 2);
            }
            #pragma unroll
            for (int mt = 0; mt < 2; mt++)
                #pragma unroll
                for (int nt = 0; nt < 4; nt++)
                    mma_bf16(acc[mt][nt], Afh[mt], Bfh[nt]);
            #pragma unroll
            for (int mt = 0; mt < 2; mt++)
                #pragma unroll
                for (int nt = 0; nt < 4; nt++)
                    mma_bf16(acc[mt][nt], Afl[mt], Bfh[nt]);
            #pragma unroll
            for (int mt = 0; mt < 2; mt++)
                #pragma unroll
                for (int nt = 0; nt < 4; nt++)
                    mma_bf16(acc[mt][nt], Afh[mt], Bfl[nt]);
        }

        if (it + 1 < nIter) {
            __nv_bfloat16* bp = sm + (buf ^ 1) * BUF_ELEMS;
            *(uint4*)(bp + AH_OFF + aRow * APITCH + aK16)     = va0;
            *(uint4*)(bp + AH_OFF + aRow * APITCH + aK16 + 8) = va1;
            *(uint4*)(bp + AL_OFF + aRow * APITCH + aK16)     = vl0;
            *(uint4*)(bp + AL_OFF + aRow * APITCH + aK16 + 8) = vl1;
            *(uint4*)(bp + BH_OFF + bK * BPITCH + bN8) = vbh;
            *(uint4*)(bp + BL_OFF + bK * BPITCH + bN8) = vbl;
        }
        __syncthreads();
        buf ^= 1;
    }

    // epilogue
    #pragma unroll
    for (int mt = 0; mt < 2; mt++) {
        #pragma unroll
        for (int nt = 0; nt < 4; nt++) {
            int col = col0 + wn + nt * 8 + 2 * qt;
            long r0 = row0 + wm + mt * 16 + g;
            float b0v = bias[col], b1v = bias[col + 1];
            float2 v0 = make_float2(acc[mt][nt][0] + b0v, acc[mt][nt][1] + b1v);
            float2 v1 = make_float2(acc[mt][nt][2] + b0v, acc[mt][nt][3] + b1v);
            if (relu) {
                v0.x = fmaxf(v0.x, 0.f); v0.y = fmaxf(v0.y, 0.f);
                v1.x = fmaxf(v1.x, 0.f); v1.y = fmaxf(v1.y, 0.f);
            }
            if (splitOut) {
                unsigned short h0, l0, h1, l1;
                split1(v0.x, h0, l0); split1(v0.y, h1, l1);
                *(unsigned*)(Ch + r0 * ldc + col) = (unsigned)h0 | ((unsigned)h1 << 16);
                *(unsigned*)(Cl + r0 * ldc + col) = (unsigned)l0 | ((unsigned)l1 << 16);
                split1(v1.x, h0, l0); split1(v1.y, h1, l1);
                *(unsigned*)(Ch + (r0 + 8) * ldc + col) = (unsigned)h0 | ((unsigned)h1 << 16);
                *(unsigned*)(Cl + (r0 + 8) * ldc + col) = (unsigned)l0 | ((unsigned)l1 << 16);
            } else {
                *(float2*)&C[r0 * ldc + col] = v0;
                *(float2*)&C[(r0 + 8) * ldc + col] = v1;
            }
        }
    }
}

// ---------------------------------------------------------------------------
// Scalar FFMA SGEMM for the small tower layers.
// ---------------------------------------------------------------------------
#define BM 128
#define BN 128
#define BK 8
#define TM 8
#define TN 8

__global__ __launch_bounds__(256)
void sgemm_bias(const float* __restrict__ A, const float* __restrict__ Bw,
                const float* __restrict__ bias, float* __restrict__ C,
                int N, int K, int lda, int ldb, int ldc,
                long aStride, int aDiv, long bStride, long biasStride, long cStride,
                int relu)
{
    int z = blockIdx.z;
    A    += (long)(z / aDiv) * aStride;
    Bw   += (long)z * bStride;
    bias += (long)z * biasStride;
    C    += (long)z * cStride;

    __shared__ float As[BK][BM];
    __shared__ float Bs[BK][BN];

    int tid  = threadIdx.x;
    int row0 = blockIdx.x * BM;
    int col0 = blockIdx.y * BN;
    int tx = tid % 16;
    int ty = tid / 16;

    int aRow = tid >> 1;
    int aCol = (tid & 1) * 4;
    int bRow = tid >> 5;
    int bCol = (tid & 31) * 4;
    bool bOk = (col0 + bCol) < N;

    float acc[TM][TN];
    #pragma unroll
    for (int i = 0; i < TM; i++)
        #pragma unroll
        for (int j = 0; j < TN; j++) acc[i][j] = 0.0f;

    for (int k0 = 0; k0 < K; k0 += BK) {
        float4 av = *(const float4*)&A[(long)(row0 + aRow) * lda + k0 + aCol];
        As[aCol + 0][aRow] = av.x;
        As[aCol + 1][aRow] = av.y;
        As[aCol + 2][aRow] = av.z;
        As[aCol + 3][aRow] = av.w;
        if (bOk) {
            float4 bv = *(const float4*)&Bw[(long)(k0 + bRow) * ldb + col0 + bCol];
            *(float4*)&Bs[bRow][bCol] = bv;
        }
        __syncthreads();

        #pragma unroll
        for (int kk = 0; kk < BK; kk++) {
            float4 a0 = *(const float4*)&As[kk][ty * TM];
            float4 a1 = *(const float4*)&As[kk][ty * TM + 4];
            float4 b0 = *(const float4*)&Bs[kk][tx * TN];
            float4 b1 = *(const float4*)&Bs[kk][tx * TN + 4];
            float ra[TM] = {a0.x, a0.y, a0.z, a0.w, a1.x, a1.y, a1.z, a1.w};
            float rbv[TN] = {b0.x, b0.y, b0.z, b0.w, b1.x, b1.y, b1.z, b1.w};
            #pragma unroll
            for (int i = 0; i < TM; i++)
                #pragma unroll
                for (int j = 0; j < TN; j++)
                    acc[i][j] += ra[i] * rbv[j];
        }
        __syncthreads();
    }

    #pragma unroll
    for (int i = 0; i < TM; i++) {
        long rr = row0 + ty * TM + i;
        #pragma unroll
        for (int j0 = 0; j0 < TN; j0 += 4) {
            int c = col0 + tx * TN + j0;
            if (c < N) {
                float4 v;
                v.x = acc[i][j0 + 0] + bias[c + 0];
                v.y = acc[i][j0 + 1] + bias[c + 1];
                v.z = acc[i][j0 + 2] + bias[c + 2];
                v.w = acc[i][j0 + 3] + bias[c + 3];
                if (relu) {
                    v.x = fmaxf(v.x, 0.f); v.y = fmaxf(v.y, 0.f);
                    v.z = fmaxf(v.z, 0.f); v.w = fmaxf(v.w, 0.f);
                }
                *(float4*)&C[rr * ldc + c] = v;
            }
        }
    }
}

// ---------------------------------------------------------------------------
__global__ void gate2_softmax_kernel(const float* __restrict__ W2,
                                     const float* __restrict__ b2) {
    int t = blockIdx.y;
    __shared__ float sW[GHn * NEXP];
    __shared__ float sb[NEXP];
    for (int i = threadIdx.x; i < GHn * NEXP; i += blockDim.x)
        sW[i] = W2[(size_t)t * GHn * NEXP + i];
    if (threadIdx.x < NEXP) sb[threadIdx.x] = b2[t * NEXP + threadIdx.x];
    __syncthreads();

    int b = blockIdx.x * blockDim.x + threadIdx.x;
    if (b >= Bn) return;

    const float4* gr = (const float4*)(g_gh + ((size_t)b * Tn + t) * GHn);
    float acc[NEXP];
    #pragma unroll
    for (int k = 0; k < NEXP; k++) acc[k] = sb[k];
    for (int h4 = 0; h4 < GHn / 4; h4++) {
        float4 x = gr[h4];
        const float* w = sW + h4 * 4 * NEXP;
        #pragma unroll
        for (int k = 0; k < NEXP; k++)
            acc[k] += x.x * w[k] + x.y * w[NEXP + k]
                    + x.z * w[2 * NEXP + k] + x.w * w[3 * NEXP + k];
    }
    float mx = acc[0];
    #pragma unroll
    for (int k = 1; k < NEXP; k++) mx = fmaxf(mx, acc[k]);
    float sum = 0.f;
    #pragma unroll
    for (int k = 0; k < NEXP; k++) { acc[k] = expf(acc[k] - mx); sum += acc[k]; }
    float inv = 1.0f / sum;
    float* o = g_gw + ((size_t)b * Tn + t) * NEXP;
    #pragma unroll
    for (int k = 0; k < NEXP; k++) o[k] = acc[k] * inv;
}

// ---------------------------------------------------------------------------
__global__ void agg_kernel() {
    int b = blockIdx.x;
    int e = threadIdx.x;
    __shared__ float sgw[Tn * NEXP];
    if (threadIdx.x < Tn * NEXP)
        sgw[threadIdx.x] = g_gw[(size_t)b * Tn * NEXP + threadIdx.x];
    __syncthreads();
    const float* eb = g_emb + (size_t)b * NEXP * En + e;
    float a0 = 0.f, a1 = 0.f, a2 = 0.f;
    #pragma unroll
    for (int k = 0; k < NEXP; k++) {
        float v = eb[(size_t)k * En];
        a0 += sgw[k] * v;
        a1 += sgw[NEXP + k] * v;
        a2 += sgw[2 * NEXP + k] * v;
    }
    float* o = g_agg + (size_t)b * Tn * En + e;
    o[0]      = a0;
    o[En]     = a1;
    o[2 * En] = a2;
}

// ---------------------------------------------------------------------------
extern "C" void kernel_launch(void* const* d_in, const int* in_sizes, int n_in,
                              void* d_out, int out_size) {
    const float* inputs = (const float*)d_in[0];
    const float* eW1 = (const float*)d_in[1];
    const float* eb1 = (const float*)d_in[2];
    const float* eW2 = (const float*)d_in[3];
    const float* eb2 = (const float*)d_in[4];
    const float* gW1 = (const float*)d_in[5];
    const float* gb1 = (const float*)d_in[6];
    const float* gW2 = (const float*)d_in[7];
    const float* gb2 = (const float*)d_in[8];
    const float* tW1 = (const float*)d_in[9];
    const float* tb1 = (const float*)d_in[10];
    const float* tW2 = (const float*)d_in[11];
    const float* tb2 = (const float*)d_in[12];
    float* out = (float*)d_out;

    __nv_bfloat16 *p_inh, *p_inl, *p_ginh, *p_ginl, *p_h1h, *p_h1l;
    __nv_bfloat16 *p_we1h, *p_we1l, *p_we2h, *p_we2l, *p_wg1h, *p_wg1l;
    float *p_emb, *p_gh, *p_agg, *p_th;
    cudaGetSymbolAddress((void**)&p_inh,  s_inh);
    cudaGetSymbolAddress((void**)&p_inl,  s_inl);
    cudaGetSymbolAddress((void**)&p_ginh, s_ginh);
    cudaGetSymbolAddress((void**)&p_ginl, s_ginl);
    cudaGetSymbolAddress((void**)&p_h1h,  s_h1h);
    cudaGetSymbolAddress((void**)&p_h1l,  s_h1l);
    cudaGetSymbolAddress((void**)&p_we1h, s_we1h);
    cudaGetSymbolAddress((void**)&p_we1l, s_we1l);
    cudaGetSymbolAddress((void**)&p_we2h, s_we2h);
    cudaGetSymbolAddress((void**)&p_we2l, s_we2l);
    cudaGetSymbolAddress((void**)&p_wg1h, s_wg1h);
    cudaGetSymbolAddress((void**)&p_wg1l, s_wg1l);
    cudaGetSymbolAddress((void**)&p_emb,  g_emb);
    cudaGetSymbolAddress((void**)&p_gh,   g_gh);
    cudaGetSymbolAddress((void**)&p_agg,  g_agg);
    cudaGetSymbolAddress((void**)&p_th,   g_th);

    cudaFuncSetAttribute(tc_gemm, cudaFuncAttributeMaxDynamicSharedMemorySize, TC_SMEM);

    // ---- one-time conversions (inputs + weights; weights keep [K][N] layout) ----
    conv_split<<<(Bn * Gn * Dn / 4 + 255) / 256, 256>>>(inputs, p_inh, p_inl, Bn * Gn * Dn / 4);
    conv_gin<<<(Bn * Tn * Dn / 4 + 255) / 256, 256>>>(inputs);
    conv_split<<<(NEXP * Dn * Hn / 4 + 255) / 256, 256>>>(eW1, p_we1h, p_we1l, NEXP * Dn * Hn / 4);
    conv_split<<<(NEXP * Hn * En / 4 + 255) / 256, 256>>>(eW2, p_we2h, p_we2l, NEXP * Hn * En / 4);
    conv_split<<<(Tn * Dn * GHn / 4 + 255) / 256, 256>>>(gW1, p_wg1h, p_wg1l, Tn * Dn * GHn / 4);

    // ---- expert layer 1: h1(bf16 hi/lo) = relu(in @ eW1 + b1) ----
    tc_gemm<<<dim3(Bn / 128, Hn / 64, NEXP), 256, TC_SMEM>>>(
        p_inh, p_inl, p_we1h, p_we1l, eb1,
        nullptr, p_h1h, p_h1l,
        Dn, Gn * Dn, Hn, NEXP * Hn,
        (long)Dn, NEn, (long)Dn * Hn, (long)Hn, (long)Hn, 1, 1);

    // ---- expert layer 2: emb(fp32) = h1 @ eW2 + b2 ----
    tc_gemm<<<dim3(Bn / 128, En / 64, NEXP), 256, TC_SMEM>>>(
        p_h1h, p_h1l, p_we2h, p_we2l, eb2,
        p_emb, nullptr, nullptr,
        Hn, NEXP * Hn, En, NEXP * En,
        (long)Hn, 1, (long)Hn * En, (long)En, (long)En, 0, 0);

    // ---- gate layer 1: gh(fp32) = relu(gin @ gW1 + b1) ----
    tc_gemm<<<dim3(Bn / 128, GHn / 64, Tn), 256, TC_SMEM>>>(
        p_ginh, p_ginl, p_wg1h, p_wg1l, gb1,
        p_gh, nullptr, nullptr,
        Dn, Tn * Dn, GHn, Tn * GHn,
        (long)Dn, 1, (long)Dn * GHn, (long)GHn, (long)GHn, 1, 0);

    gate2_softmax_kernel<<<dim3(Bn / 256, Tn), 256>>>(gW2, gb2);

    agg_kernel<<<Bn, En>>>();

    sgemm_bias<<<dim3(Bn / BM, 1, Tn), 256>>>(
        p_agg, tW1, tb1, p_th,
        THn, En, Tn * En, THn, Tn * THn,
        (long)En, 1, (long)En * THn, (long)THn, (long)THn, 1);

    sgemm_bias<<<dim3(Bn / BM, 1, Tn), 256>>>(
        p_th, tW2, tb2, out,
        TOn, THn, Tn * THn, TOn, Tn * TOn,
        (long)THn, 1, (long)THn * TOn, (long)TOn, (long)TOn, 0);
}

// round 7
// speedup vs baseline: 3.1374x; 1.5911x over previous
#include <cuda_runtime.h>
#include <cuda_fp16.h>
#include <cstdint>
#include <math.h>

// Problem dims
#define Bn   16384
#define Tn   3
#define Dn   512
#define Gn   4
#define NEn  4
#define NEXP 16
#define Hn   512
#define En   256
#define GHn  256
#define THn  128
#define TOn  64

// ---------------- scratch (device globals; no allocs allowed) ----------------
__device__ __half s_in  [(size_t)Bn * Gn * Dn];          // inputs, fp16
__device__ __half s_gin [(size_t)Bn * Tn * Dn];          // gate inputs, fp16
__device__ __half s_h1  [(size_t)Bn * NEXP * Hn];        // h1, fp16
__device__ __half s_we1h[(size_t)NEXP * Dn * Hn];        // [e][D][H] hi
__device__ __half s_we1l[(size_t)NEXP * Dn * Hn];        // lo
__device__ __half s_we2h[(size_t)NEXP * Hn * En];
__device__ __half s_we2l[(size_t)NEXP * Hn * En];
__device__ __half s_wg1h[(size_t)Tn * Dn * GHn];
__device__ __half s_wg1l[(size_t)Tn * Dn * GHn];
__device__ float g_emb[(size_t)Bn * NEXP * En];
__device__ float g_gh [(size_t)Bn * Tn * GHn];
__device__ float g_gw [(size_t)Bn * Tn * NEXP];
__device__ float g_agg[(size_t)Bn * Tn * En];
__device__ float g_th [(size_t)Bn * Tn * THn];

// ---------------- helpers ----------------
__device__ __forceinline__ void hsplit1(float x, unsigned short& h, unsigned short& l) {
    __half hb = __float2half_rn(x);
    __half lb = __float2half_rn(x - __half2float(hb));
    h = __half_as_ushort(hb);
    l = __half_as_ushort(lb);
}
__device__ __forceinline__ uint2 pack_h4(float4 v) {
    uint2 r;
    r.x = (unsigned)__half_as_ushort(__float2half_rn(v.x))
        | ((unsigned)__half_as_ushort(__float2half_rn(v.y)) << 16);
    r.y = (unsigned)__half_as_ushort(__float2half_rn(v.z))
        | ((unsigned)__half_as_ushort(__float2half_rn(v.w)) << 16);
    return r;
}

// ---------------- conversion kernels ----------------
__global__ void conv_half(const float* __restrict__ in, __half* __restrict__ o, int n4) {
    int i = blockIdx.x * blockDim.x + threadIdx.x;
    if (i >= n4) return;
    ((uint2*)o)[i] = pack_h4(((const float4*)in)[i]);
}

__global__ void conv_gin(const float* __restrict__ in) {
    int i = blockIdx.x * blockDim.x + threadIdx.x;
    int total = Bn * Tn * Dn / 4;
    if (i >= total) return;
    int d4 = i % (Dn / 4);
    int bt = i / (Dn / 4);
    int t  = bt % Tn;
    int b  = bt / Tn;
    const float4* base = (const float4*)(in + (size_t)b * Gn * Dn);
    float4 a = base[(size_t)(t + 1) * (Dn / 4) + d4];
    float4 s = base[d4];
    ((uint2*)s_gin)[i] = pack_h4(make_float4(a.x + s.x, a.y + s.y, a.z + s.z, a.w + s.w));
}

__global__ void conv_wsplit(const float* __restrict__ W,
                            __half* __restrict__ Wh, __half* __restrict__ Wl, int n) {
    int i = blockIdx.x * blockDim.x + threadIdx.x;
    if (i >= n) return;
    unsigned short h, l;
    hsplit1(W[i], h, l);
    Wh[i] = __ushort_as_half(h);
    Wl[i] = __ushort_as_half(l);
}

// ===========================================================================
// Tensor-core batched GEMM: fp16 A (single), fp16 B hi/lo (2-term split).
// A [M,K] row-major; B [K,N] row-major. C = A@(Bh+Bl) + bias [+relu].
// Block tile 128x64x32, 256 threads (8 warps: 4M x 2N), warp tile 32x32.
// ===========================================================================
#define APITCH 40
#define BPITCH 72
#define A_OFF  0
#define BH_OFF (128 * APITCH)               // 5120
#define BL_OFF (128 * APITCH + 32 * BPITCH) // 7424
#define BUF_ELEMS (128 * APITCH + 2 * 32 * BPITCH)  // 9728
#define TC_SMEM (2 * BUF_ELEMS * 2)         // 38912 bytes

__device__ __forceinline__ void mma_f16(float* c, const unsigned* a, const unsigned* b) {
    asm volatile(
        "mma.sync.aligned.m16n8k16.row.col.f32.f16.f16.f32 "
        "{%0,%1,%2,%3},{%4,%5,%6,%7},{%8,%9},{%0,%1,%2,%3};"
        : "+f"(c[0]), "+f"(c[1]), "+f"(c[2]), "+f"(c[3])
        : "r"(a[0]), "r"(a[1]), "r"(a[2]), "r"(a[3]), "r"(b[0]), "r"(b[1]));
}
__device__ __forceinline__ void ldsm4(unsigned& r0, unsigned& r1,
                                      unsigned& r2, unsigned& r3, unsigned addr) {
    asm volatile("ldmatrix.sync.aligned.m8n8.x4.shared.b16 {%0,%1,%2,%3},[%4];"
                 : "=r"(r0), "=r"(r1), "=r"(r2), "=r"(r3) : "r"(addr));
}
__device__ __forceinline__ void ldsm4t(unsigned& r0, unsigned& r1,
                                       unsigned& r2, unsigned& r3, unsigned addr) {
    asm volatile("ldmatrix.sync.aligned.m8n8.x4.trans.shared.b16 {%0,%1,%2,%3},[%4];"
                 : "=r"(r0), "=r"(r1), "=r"(r2), "=r"(r3) : "r"(addr));
}

__global__ void __launch_bounds__(256, 2)
tc_gemm(const __half* __restrict__ A,
        const __half* __restrict__ Bh, const __half* __restrict__ Bl,
        const float* __restrict__ bias,
        float* __restrict__ C, __half* __restrict__ Chalf,
        int K, int lda, int ldb, int ldc,
        long aStride, int aDiv, long bStride, long biasStride, long cStride,
        int relu, int halfOut)
{
    extern __shared__ __half sm[];
    int z = blockIdx.z;
    A  += (long)(z / aDiv) * aStride;
    Bh += (long)z * bStride;
    Bl += (long)z * bStride;
    bias += (long)z * biasStride;
    if (halfOut) Chalf += (long)z * cStride;
    else         C     += (long)z * cStride;

    int tid  = threadIdx.x;
    int lane = tid & 31, warp = tid >> 5;
    int row0 = blockIdx.x * 128, col0 = blockIdx.y * 64;
    int wm = (warp >> 1) * 32, wn = (warp & 1) * 32;
    int g = lane >> 2, qt = lane & 3;

    unsigned sbase = (unsigned)__cvta_generic_to_shared(sm);

    // ldmatrix per-lane offsets
    int rA = (lane & 7) + ((lane >> 3) & 1) * 8;
    int cA = ((lane >> 4) & 1) * 8;
    int rB = (lane & 7) + ((lane >> 3) & 1) * 8;
    int cB = ((lane >> 4) & 1) * 8;

    // gmem load mapping
    int aRow = tid >> 2;            // 0..63 (+64)
    int aK8  = (tid & 3) * 8;       // one uint4 (8 halves) along K
    int bK   = tid >> 3;            // 0..31
    int bN8  = (tid & 7) * 8;       // 8 halves along N

    float acc[2][4][4];
    #pragma unroll
    for (int i = 0; i < 2; i++)
        #pragma unroll
        for (int j = 0; j < 4; j++)
            #pragma unroll
            for (int k = 0; k < 4; k++) acc[i][j][k] = 0.0f;

    const __half* aSrc0 = A + (long)(row0 + aRow) * lda + aK8;
    const __half* aSrc1 = A + (long)(row0 + aRow + 64) * lda + aK8;
    const __half* bSrcH = Bh + (long)bK * ldb + col0 + bN8;
    const __half* bSrcL = Bl + (long)bK * ldb + col0 + bN8;

    uint4 va0, va1, vbh, vbl;
    int nIter = K / 32;

    // prefetch tile 0
    va0 = *(const uint4*)(aSrc0);
    va1 = *(const uint4*)(aSrc1);
    vbh = *(const uint4*)(bSrcH);
    vbl = *(const uint4*)(bSrcL);

    // store tile 0
    {
        __half* bp = sm;
        *(uint4*)(bp + A_OFF + aRow * APITCH + aK8)          = va0;
        *(uint4*)(bp + A_OFF + (aRow + 64) * APITCH + aK8)   = va1;
        *(uint4*)(bp + BH_OFF + bK * BPITCH + bN8) = vbh;
        *(uint4*)(bp + BL_OFF + bK * BPITCH + bN8) = vbl;
    }
    __syncthreads();

    int buf = 0;
    for (int it = 0; it < nIter; it++) {
        if (it + 1 < nIter) {
            int k0 = (it + 1) * 32;
            va0 = *(const uint4*)(aSrc0 + k0);
            va1 = *(const uint4*)(aSrc1 + k0);
            vbh = *(const uint4*)(bSrcH + (long)k0 * ldb);
            vbl = *(const uint4*)(bSrcL + (long)k0 * ldb);
        }

        unsigned bufb = sbase + buf * (BUF_ELEMS * 2);

        #pragma unroll
        for (int ks = 0; ks < 32; ks += 16) {
            unsigned Af[2][4], Bfh[4][2], Bfl[4][2];
            #pragma unroll
            for (int mt = 0; mt < 2; mt++) {
                unsigned ad = bufb + (A_OFF + (wm + mt * 16 + rA) * APITCH + ks + cA) * 2;
                ldsm4(Af[mt][0], Af[mt][1], Af[mt][2], Af[mt][3], ad);
            }
            #pragma unroll
            for (int np = 0; np < 2; np++) {
                unsigned bd = bufb + (BH_OFF + (ks + rB) * BPITCH + wn + np * 16 + cB) * 2;
                ldsm4t(Bfh[2*np][0], Bfh[2*np][1], Bfh[2*np+1][0], Bfh[2*np+1][1], bd);
                ldsm4t(Bfl[2*np][0], Bfl[2*np][1], Bfl[2*np+1][0], Bfl[2*np+1][1],
                       bd + (BL_OFF - BH_OFF) * 2);
            }
            #pragma unroll
            for (int mt = 0; mt < 2; mt++)
                #pragma unroll
                for (int nt = 0; nt < 4; nt++)
                    mma_f16(acc[mt][nt], Af[mt], Bfh[nt]);
            #pragma unroll
            for (int mt = 0; mt < 2; mt++)
                #pragma unroll
                for (int nt = 0; nt < 4; nt++)
                    mma_f16(acc[mt][nt], Af[mt], Bfl[nt]);
        }

        if (it + 1 < nIter) {
            __half* bp = sm + (buf ^ 1) * BUF_ELEMS;
            *(uint4*)(bp + A_OFF + aRow * APITCH + aK8)        = va0;
            *(uint4*)(bp + A_OFF + (aRow + 64) * APITCH + aK8) = va1;
            *(uint4*)(bp + BH_OFF + bK * BPITCH + bN8) = vbh;
            *(uint4*)(bp + BL_OFF + bK * BPITCH + bN8) = vbl;
        }
        __syncthreads();
        buf ^= 1;
    }

    // epilogue
    #pragma unroll
    for (int mt = 0; mt < 2; mt++) {
        #pragma unroll
        for (int nt = 0; nt < 4; nt++) {
            int col = col0 + wn + nt * 8 + 2 * qt;
            long r0 = row0 + wm + mt * 16 + g;
            float b0v = bias[col], b1v = bias[col + 1];
            float2 v0 = make_float2(acc[mt][nt][0] + b0v, acc[mt][nt][1] + b1v);
            float2 v1 = make_float2(acc[mt][nt][2] + b0v, acc[mt][nt][3] + b1v);
            if (relu) {
                v0.x = fmaxf(v0.x, 0.f); v0.y = fmaxf(v0.y, 0.f);
                v1.x = fmaxf(v1.x, 0.f); v1.y = fmaxf(v1.y, 0.f);
            }
            if (halfOut) {
                *(unsigned*)(Chalf + r0 * ldc + col) =
                    (unsigned)__half_as_ushort(__float2half_rn(v0.x))
                  | ((unsigned)__half_as_ushort(__float2half_rn(v0.y)) << 16);
                *(unsigned*)(Chalf + (r0 + 8) * ldc + col) =
                    (unsigned)__half_as_ushort(__float2half_rn(v1.x))
                  | ((unsigned)__half_as_ushort(__float2half_rn(v1.y)) << 16);
            } else {
                *(float2*)&C[r0 * ldc + col] = v0;
                *(float2*)&C[(r0 + 8) * ldc + col] = v1;
            }
        }
    }
}

// ---------------------------------------------------------------------------
// Scalar FFMA SGEMM for the small tower layers.
// ---------------------------------------------------------------------------
#define BM 128
#define BN 128
#define BK 8
#define TM 8
#define TN 8

__global__ __launch_bounds__(256)
void sgemm_bias(const float* __restrict__ A, const float* __restrict__ Bw,
                const float* __restrict__ bias, float* __restrict__ C,
                int N, int K, int lda, int ldb, int ldc,
                long aStride, int aDiv, long bStride, long biasStride, long cStride,
                int relu)
{
    int z = blockIdx.z;
    A    += (long)(z / aDiv) * aStride;
    Bw   += (long)z * bStride;
    bias += (long)z * biasStride;
    C    += (long)z * cStride;

    __shared__ float As[BK][BM];
    __shared__ float Bs[BK][BN];

    int tid  = threadIdx.x;
    int row0 = blockIdx.x * BM;
    int col0 = blockIdx.y * BN;
    int tx = tid % 16;
    int ty = tid / 16;

    int aRow = tid >> 1;
    int aCol = (tid & 1) * 4;
    int bRow = tid >> 5;
    int bCol = (tid & 31) * 4;
    bool bOk = (col0 + bCol) < N;

    float acc[TM][TN];
    #pragma unroll
    for (int i = 0; i < TM; i++)
        #pragma unroll
        for (int j = 0; j < TN; j++) acc[i][j] = 0.0f;

    for (int k0 = 0; k0 < K; k0 += BK) {
        float4 av = *(const float4*)&A[(long)(row0 + aRow) * lda + k0 + aCol];
        As[aCol + 0][aRow] = av.x;
        As[aCol + 1][aRow] = av.y;
        As[aCol + 2][aRow] = av.z;
        As[aCol + 3][aRow] = av.w;
        if (bOk) {
            float4 bv = *(const float4*)&Bw[(long)(k0 + bRow) * ldb + col0 + bCol];
            *(float4*)&Bs[bRow][bCol] = bv;
        }
        __syncthreads();

        #pragma unroll
        for (int kk = 0; kk < BK; kk++) {
            float4 a0 = *(const float4*)&As[kk][ty * TM];
            float4 a1 = *(const float4*)&As[kk][ty * TM + 4];
            float4 b0 = *(const float4*)&Bs[kk][tx * TN];
            float4 b1 = *(const float4*)&Bs[kk][tx * TN + 4];
            float ra[TM] = {a0.x, a0.y, a0.z, a0.w, a1.x, a1.y, a1.z, a1.w};
            float rbv[TN] = {b0.x, b0.y, b0.z, b0.w, b1.x, b1.y, b1.z, b1.w};
            #pragma unroll
            for (int i = 0; i < TM; i++)
                #pragma unroll
                for (int j = 0; j < TN; j++)
                    acc[i][j] += ra[i] * rbv[j];
        }
        __syncthreads();
    }

    #pragma unroll
    for (int i = 0; i < TM; i++) {
        long rr = row0 + ty * TM + i;
        #pragma unroll
        for (int j0 = 0; j0 < TN; j0 += 4) {
            int c = col0 + tx * TN + j0;
            if (c < N) {
                float4 v;
                v.x = acc[i][j0 + 0] + bias[c + 0];
                v.y = acc[i][j0 + 1] + bias[c + 1];
                v.z = acc[i][j0 + 2] + bias[c + 2];
                v.w = acc[i][j0 + 3] + bias[c + 3];
                if (relu) {
                    v.x = fmaxf(v.x, 0.f); v.y = fmaxf(v.y, 0.f);
                    v.z = fmaxf(v.z, 0.f); v.w = fmaxf(v.w, 0.f);
                }
                *(float4*)&C[rr * ldc + c] = v;
            }
        }
    }
}

// ---------------------------------------------------------------------------
__global__ void gate2_softmax_kernel(const float* __restrict__ W2,
                                     const float* __restrict__ b2) {
    int t = blockIdx.y;
    __shared__ float sW[GHn * NEXP];
    __shared__ float sb[NEXP];
    for (int i = threadIdx.x; i < GHn * NEXP; i += blockDim.x)
        sW[i] = W2[(size_t)t * GHn * NEXP + i];
    if (threadIdx.x < NEXP) sb[threadIdx.x] = b2[t * NEXP + threadIdx.x];
    __syncthreads();

    int b = blockIdx.x * blockDim.x + threadIdx.x;
    if (b >= Bn) return;

    const float4* gr = (const float4*)(g_gh + ((size_t)b * Tn + t) * GHn);
    float acc[NEXP];
    #pragma unroll
    for (int k = 0; k < NEXP; k++) acc[k] = sb[k];
    for (int h4 = 0; h4 < GHn / 4; h4++) {
        float4 x = gr[h4];
        const float* w = sW + h4 * 4 * NEXP;
        #pragma unroll
        for (int k = 0; k < NEXP; k++)
            acc[k] += x.x * w[k] + x.y * w[NEXP + k]
                    + x.z * w[2 * NEXP + k] + x.w * w[3 * NEXP + k];
    }
    float mx = acc[0];
    #pragma unroll
    for (int k = 1; k < NEXP; k++) mx = fmaxf(mx, acc[k]);
    float sum = 0.f;
    #pragma unroll
    for (int k = 0; k < NEXP; k++) { acc[k] = expf(acc[k] - mx); sum += acc[k]; }
    float inv = 1.0f / sum;
    float* o = g_gw + ((size_t)b * Tn + t) * NEXP;
    #pragma unroll
    for (int k = 0; k < NEXP; k++) o[k] = acc[k] * inv;
}

// ---------------------------------------------------------------------------
__global__ void agg_kernel() {
    int b = blockIdx.x;
    int e = threadIdx.x;
    __shared__ float sgw[Tn * NEXP];
    if (threadIdx.x < Tn * NEXP)
        sgw[threadIdx.x] = g_gw[(size_t)b * Tn * NEXP + threadIdx.x];
    __syncthreads();
    const float* eb = g_emb + (size_t)b * NEXP * En + e;
    float a0 = 0.f, a1 = 0.f, a2 = 0.f;
    #pragma unroll
    for (int k = 0; k < NEXP; k++) {
        float v = eb[(size_t)k * En];
        a0 += sgw[k] * v;
        a1 += sgw[NEXP + k] * v;
        a2 += sgw[2 * NEXP + k] * v;
    }
    float* o = g_agg + (size_t)b * Tn * En + e;
    o[0]      = a0;
    o[En]     = a1;
    o[2 * En] = a2;
}

// ---------------------------------------------------------------------------
extern "C" void kernel_launch(void* const* d_in, const int* in_sizes, int n_in,
                              void* d_out, int out_size) {
    const float* inputs = (const float*)d_in[0];
    const float* eW1 = (const float*)d_in[1];
    const float* eb1 = (const float*)d_in[2];
    const float* eW2 = (const float*)d_in[3];
    const float* eb2 = (const float*)d_in[4];
    const float* gW1 = (const float*)d_in[5];
    const float* gb1 = (const float*)d_in[6];
    const float* gW2 = (const float*)d_in[7];
    const float* gb2 = (const float*)d_in[8];
    const float* tW1 = (const float*)d_in[9];
    const float* tb1 = (const float*)d_in[10];
    const float* tW2 = (const float*)d_in[11];
    const float* tb2 = (const float*)d_in[12];
    float* out = (float*)d_out;

    __half *p_in, *p_gin, *p_h1;
    __half *p_we1h, *p_we1l, *p_we2h, *p_we2l, *p_wg1h, *p_wg1l;
    float *p_emb, *p_gh, *p_agg, *p_th;
    cudaGetSymbolAddress((void**)&p_in,   s_in);
    cudaGetSymbolAddress((void**)&p_gin,  s_gin);
    cudaGetSymbolAddress((void**)&p_h1,   s_h1);
    cudaGetSymbolAddress((void**)&p_we1h, s_we1h);
    cudaGetSymbolAddress((void**)&p_we1l, s_we1l);
    cudaGetSymbolAddress((void**)&p_we2h, s_we2h);
    cudaGetSymbolAddress((void**)&p_we2l, s_we2l);
    cudaGetSymbolAddress((void**)&p_wg1h, s_wg1h);
    cudaGetSymbolAddress((void**)&p_wg1l, s_wg1l);
    cudaGetSymbolAddress((void**)&p_emb,  g_emb);
    cudaGetSymbolAddress((void**)&p_gh,   g_gh);
    cudaGetSymbolAddress((void**)&p_agg,  g_agg);
    cudaGetSymbolAddress((void**)&p_th,   g_th);

    cudaFuncSetAttribute(tc_gemm, cudaFuncAttributeMaxDynamicSharedMemorySize, TC_SMEM);

    // ---- one-time conversions ----
    conv_half<<<(Bn * Gn * Dn / 4 + 255) / 256, 256>>>(inputs, p_in, Bn * Gn * Dn / 4);
    conv_gin<<<(Bn * Tn * Dn / 4 + 255) / 256, 256>>>(inputs);
    conv_wsplit<<<(NEXP * Dn * Hn + 255) / 256, 256>>>(eW1, p_we1h, p_we1l, NEXP * Dn * Hn);
    conv_wsplit<<<(NEXP * Hn * En + 255) / 256, 256>>>(eW2, p_we2h, p_we2l, NEXP * Hn * En);
    conv_wsplit<<<(Tn * Dn * GHn + 255) / 256, 256>>>(gW1, p_wg1h, p_wg1l, Tn * Dn * GHn);

    // ---- expert layer 1: h1(fp16) = relu(in @ eW1 + b1) ----
    tc_gemm<<<dim3(Bn / 128, Hn / 64, NEXP), 256, TC_SMEM>>>(
        p_in, p_we1h, p_we1l, eb1,
        nullptr, p_h1,
        Dn, Gn * Dn, Hn, NEXP * Hn,
        (long)Dn, NEn, (long)Dn * Hn, (long)Hn, (long)Hn, 1, 1);

    // ---- expert layer 2: emb(fp32) = h1 @ eW2 + b2 ----
    tc_gemm<<<dim3(Bn / 128, En / 64, NEXP), 256, TC_SMEM>>>(
        p_h1, p_we2h, p_we2l, eb2,
        p_emb, nullptr,
        Hn, NEXP * Hn, En, NEXP * En,
        (long)Hn, 1, (long)Hn * En, (long)En, (long)En, 0, 0);

    // ---- gate layer 1: gh(fp32) = relu(gin @ gW1 + b1) ----
    tc_gemm<<<dim3(Bn / 128, GHn / 64, Tn), 256, TC_SMEM>>>(
        p_gin, p_wg1h, p_wg1l, gb1,
        p_gh, nullptr,
        Dn, Tn * Dn, GHn, Tn * GHn,
        (long)Dn, 1, (long)Dn * GHn, (long)GHn, (long)GHn, 1, 0);

    gate2_softmax_kernel<<<dim3(Bn / 256, Tn), 256>>>(gW2, gb2);

    agg_kernel<<<Bn, En>>>();

    sgemm_bias<<<dim3(Bn / BM, 1, Tn), 256>>>(
        p_agg, tW1, tb1, p_th,
        THn, En, Tn * En, THn, Tn * THn,
        (long)En, 1, (long)En * THn, (long)THn, (long)THn, 1);

    sgemm_bias<<<dim3(Bn / BM, 1, Tn), 256>>>(
        p_th, tW2, tb2, out,
        TOn, THn, Tn * THn, TOn, Tn * TOn,
        (long)THn, 1, (long)THn * TOn, (long)TOn, (long)TOn, 0);
}

// round 8
// speedup vs baseline: 4.5592x; 1.4532x over previous
#include <cuda_runtime.h>
#include <cuda_fp16.h>
#include <cstdint>
#include <math.h>

// Problem dims
#define Bn   16384
#define Tn   3
#define Dn   512
#define Gn   4
#define NEn  4
#define NEXP 16
#define Hn   512
#define En   256
#define GHn  256
#define THn  128
#define TOn  64

// ---------------- scratch (device globals; no allocs allowed) ----------------
__device__ __half s_in  [(size_t)Bn * Gn * Dn];
__device__ __half s_gin [(size_t)Bn * Tn * Dn];
__device__ __half s_h1  [(size_t)Bn * NEXP * Hn];
__device__ __half s_we1 [(size_t)NEXP * Dn * Hn];   // [e][D][H]
__device__ __half s_we2 [(size_t)NEXP * Hn * En];   // [e][H][E]
__device__ __half s_wg1 [(size_t)Tn * Dn * GHn];    // [t][D][GH]
__device__ float g_emb[(size_t)Bn * NEXP * En];
__device__ float g_gh [(size_t)Bn * Tn * GHn];
__device__ float g_gw [(size_t)Bn * Tn * NEXP];
__device__ float g_agg[(size_t)Bn * Tn * En];
__device__ float g_th [(size_t)Bn * Tn * THn];

// ---------------- helpers ----------------
__device__ __forceinline__ uint2 pack_h4(float4 v) {
    uint2 r;
    r.x = (unsigned)__half_as_ushort(__float2half_rn(v.x))
        | ((unsigned)__half_as_ushort(__float2half_rn(v.y)) << 16);
    r.y = (unsigned)__half_as_ushort(__float2half_rn(v.z))
        | ((unsigned)__half_as_ushort(__float2half_rn(v.w)) << 16);
    return r;
}

// ---------------- conversion kernels ----------------
__global__ void conv_half(const float* __restrict__ in, __half* __restrict__ o, int n4) {
    int i = blockIdx.x * blockDim.x + threadIdx.x;
    if (i >= n4) return;
    ((uint2*)o)[i] = pack_h4(((const float4*)in)[i]);
}

__global__ void conv_gin(const float* __restrict__ in) {
    int i = blockIdx.x * blockDim.x + threadIdx.x;
    int total = Bn * Tn * Dn / 4;
    if (i >= total) return;
    int d4 = i % (Dn / 4);
    int bt = i / (Dn / 4);
    int t  = bt % Tn;
    int b  = bt / Tn;
    const float4* base = (const float4*)(in + (size_t)b * Gn * Dn);
    float4 a = base[(size_t)(t + 1) * (Dn / 4) + d4];
    float4 s = base[d4];
    ((uint2*)s_gin)[i] = pack_h4(make_float4(a.x + s.x, a.y + s.y, a.z + s.z, a.w + s.w));
}

// ===========================================================================
// Tensor-core batched GEMM: single fp16 A and B.
// A [M,K] row-major; B [K,N] row-major. C = A@B + bias [+relu].
// Block tile 128x128x32, 256 threads (8 warps: 2M x 4N), warp tile 64x32.
// 2 CTAs/SM (smem 37.9KB/CTA).
// ===========================================================================
#define APITCH 40
#define BPITCH 136
#define A_OFF  0
#define B_OFF (128 * APITCH)                         // 5120
#define BUF_ELEMS (128 * APITCH + 32 * BPITCH)       // 9472
#define TC_SMEM (2 * BUF_ELEMS * 2)                  // 37888 bytes

__device__ __forceinline__ void mma_f16(float* c, const unsigned* a, const unsigned* b) {
    asm volatile(
        "mma.sync.aligned.m16n8k16.row.col.f32.f16.f16.f32 "
        "{%0,%1,%2,%3},{%4,%5,%6,%7},{%8,%9},{%0,%1,%2,%3};"
        : "+f"(c[0]), "+f"(c[1]), "+f"(c[2]), "+f"(c[3])
        : "r"(a[0]), "r"(a[1]), "r"(a[2]), "r"(a[3]), "r"(b[0]), "r"(b[1]));
}
__device__ __forceinline__ void ldsm4(unsigned& r0, unsigned& r1,
                                      unsigned& r2, unsigned& r3, unsigned addr) {
    asm volatile("ldmatrix.sync.aligned.m8n8.x4.shared.b16 {%0,%1,%2,%3},[%4];"
                 : "=r"(r0), "=r"(r1), "=r"(r2), "=r"(r3) : "r"(addr));
}
__device__ __forceinline__ void ldsm4t(unsigned& r0, unsigned& r1,
                                       unsigned& r2, unsigned& r3, unsigned addr) {
    asm volatile("ldmatrix.sync.aligned.m8n8.x4.trans.shared.b16 {%0,%1,%2,%3},[%4];"
                 : "=r"(r0), "=r"(r1), "=r"(r2), "=r"(r3) : "r"(addr));
}

__global__ void __launch_bounds__(256, 2)
tc_gemm(const __half* __restrict__ A, const __half* __restrict__ Bw,
        const float* __restrict__ bias,
        float* __restrict__ C, __half* __restrict__ Chalf,
        int K, int lda, int ldb, int ldc,
        long aStride, int aDiv, long bStride, long biasStride, long cStride,
        int relu, int halfOut)
{
    extern __shared__ __half sm[];
    int z = blockIdx.z;
    A  += (long)(z / aDiv) * aStride;
    Bw += (long)z * bStride;
    bias += (long)z * biasStride;
    if (halfOut) Chalf += (long)z * cStride;
    else         C     += (long)z * cStride;

    int tid  = threadIdx.x;
    int lane = tid & 31, warp = tid >> 5;
    int row0 = blockIdx.x * 128, col0 = blockIdx.y * 128;
    int wm = (warp >> 2) * 64, wn = (warp & 3) * 32;
    int g = lane >> 2, qt = lane & 3;

    unsigned sbase = (unsigned)__cvta_generic_to_shared(sm);

    // ldmatrix per-lane offsets
    int rA = (lane & 7) + ((lane >> 3) & 1) * 8;
    int cA = ((lane >> 4) & 1) * 8;
    int rB = (lane & 7) + ((lane >> 3) & 1) * 8;
    int cB = ((lane >> 4) & 1) * 8;

    // gmem load mapping
    int aRow = tid >> 2;            // 0..63 (+64)
    int aK8  = (tid & 3) * 8;       // one uint4 along K (x2 rows)
    int bK   = tid >> 3;            // 0..31
    int bN16 = (tid & 7) * 16;      // two uint4 along N

    float acc[4][4][4];
    #pragma unroll
    for (int i = 0; i < 4; i++)
        #pragma unroll
        for (int j = 0; j < 4; j++)
            #pragma unroll
            for (int k = 0; k < 4; k++) acc[i][j][k] = 0.0f;

    const __half* aSrc0 = A + (long)(row0 + aRow) * lda + aK8;
    const __half* aSrc1 = A + (long)(row0 + aRow + 64) * lda + aK8;
    const __half* bSrc  = Bw + (long)bK * ldb + col0 + bN16;

    uint4 va0, va1, vb0, vb1;
    int nIter = K / 32;

    // prefetch tile 0
    va0 = *(const uint4*)(aSrc0);
    va1 = *(const uint4*)(aSrc1);
    vb0 = *(const uint4*)(bSrc);
    vb1 = *(const uint4*)(bSrc + 8);

    // store tile 0
    {
        __half* bp = sm;
        *(uint4*)(bp + A_OFF + aRow * APITCH + aK8)        = va0;
        *(uint4*)(bp + A_OFF + (aRow + 64) * APITCH + aK8) = va1;
        *(uint4*)(bp + B_OFF + bK * BPITCH + bN16)     = vb0;
        *(uint4*)(bp + B_OFF + bK * BPITCH + bN16 + 8) = vb1;
    }
    __syncthreads();

    int buf = 0;
    for (int it = 0; it < nIter; it++) {
        if (it + 1 < nIter) {
            int k0 = (it + 1) * 32;
            va0 = *(const uint4*)(aSrc0 + k0);
            va1 = *(const uint4*)(aSrc1 + k0);
            vb0 = *(const uint4*)(bSrc + (long)k0 * ldb);
            vb1 = *(const uint4*)(bSrc + (long)k0 * ldb + 8);
        }

        unsigned bufb = sbase + buf * (BUF_ELEMS * 2);

        #pragma unroll
        for (int ks = 0; ks < 32; ks += 16) {
            unsigned Af[4][4], Bf[4][2];
            #pragma unroll
            for (int mt = 0; mt < 4; mt += 2) {
                unsigned ad = bufb + (A_OFF + (wm + mt * 16 + rA) * APITCH + ks + cA) * 2;
                ldsm4(Af[mt][0], Af[mt][1], Af[mt][2], Af[mt][3], ad);
                unsigned ad2 = bufb + (A_OFF + (wm + (mt + 1) * 16 + rA) * APITCH + ks + cA) * 2;
                ldsm4(Af[mt+1][0], Af[mt+1][1], Af[mt+1][2], Af[mt+1][3], ad2);
            }
            #pragma unroll
            for (int np = 0; np < 2; np++) {
                unsigned bd = bufb + (B_OFF + (ks + rB) * BPITCH + wn + np * 16 + cB) * 2;
                ldsm4t(Bf[2*np][0], Bf[2*np][1], Bf[2*np+1][0], Bf[2*np+1][1], bd);
            }
            #pragma unroll
            for (int mt = 0; mt < 4; mt++)
                #pragma unroll
                for (int nt = 0; nt < 4; nt++)
                    mma_f16(acc[mt][nt], Af[mt], Bf[nt]);
        }

        if (it + 1 < nIter) {
            __half* bp = sm + (buf ^ 1) * BUF_ELEMS;
            *(uint4*)(bp + A_OFF + aRow * APITCH + aK8)        = va0;
            *(uint4*)(bp + A_OFF + (aRow + 64) * APITCH + aK8) = va1;
            *(uint4*)(bp + B_OFF + bK * BPITCH + bN16)     = vb0;
            *(uint4*)(bp + B_OFF + bK * BPITCH + bN16 + 8) = vb1;
        }
        __syncthreads();
        buf ^= 1;
    }

    // epilogue
    #pragma unroll
    for (int mt = 0; mt < 4; mt++) {
        #pragma unroll
        for (int nt = 0; nt < 4; nt++) {
            int col = col0 + wn + nt * 8 + 2 * qt;
            long r0 = row0 + wm + mt * 16 + g;
            float b0v = bias[col], b1v = bias[col + 1];
            float2 v0 = make_float2(acc[mt][nt][0] + b0v, acc[mt][nt][1] + b1v);
            float2 v1 = make_float2(acc[mt][nt][2] + b0v, acc[mt][nt][3] + b1v);
            if (relu) {
                v0.x = fmaxf(v0.x, 0.f); v0.y = fmaxf(v0.y, 0.f);
                v1.x = fmaxf(v1.x, 0.f); v1.y = fmaxf(v1.y, 0.f);
            }
            if (halfOut) {
                *(unsigned*)(Chalf + r0 * ldc + col) =
                    (unsigned)__half_as_ushort(__float2half_rn(v0.x))
                  | ((unsigned)__half_as_ushort(__float2half_rn(v0.y)) << 16);
                *(unsigned*)(Chalf + (r0 + 8) * ldc + col) =
                    (unsigned)__half_as_ushort(__float2half_rn(v1.x))
                  | ((unsigned)__half_as_ushort(__float2half_rn(v1.y)) << 16);
            } else {
                *(float2*)&C[r0 * ldc + col] = v0;
                *(float2*)&C[(r0 + 8) * ldc + col] = v1;
            }
        }
    }
}

// ---------------------------------------------------------------------------
// Scalar FFMA SGEMM for the small tower layers.
// ---------------------------------------------------------------------------
#define BM 128
#define BN 128
#define BK 8
#define TM 8
#define TN 8

__global__ __launch_bounds__(256)
void sgemm_bias(const float* __restrict__ A, const float* __restrict__ Bw,
                const float* __restrict__ bias, float* __restrict__ C,
                int N, int K, int lda, int ldb, int ldc,
                long aStride, int aDiv, long bStride, long biasStride, long cStride,
                int relu)
{
    int z = blockIdx.z;
    A    += (long)(z / aDiv) * aStride;
    Bw   += (long)z * bStride;
    bias += (long)z * biasStride;
    C    += (long)z * cStride;

    __shared__ float As[BK][BM];
    __shared__ float Bs[BK][BN];

    int tid  = threadIdx.x;
    int row0 = blockIdx.x * BM;
    int col0 = blockIdx.y * BN;
    int tx = tid % 16;
    int ty = tid / 16;

    int aRow = tid >> 1;
    int aCol = (tid & 1) * 4;
    int bRow = tid >> 5;
    int bCol = (tid & 31) * 4;
    bool bOk = (col0 + bCol) < N;

    float acc[TM][TN];
    #pragma unroll
    for (int i = 0; i < TM; i++)
        #pragma unroll
        for (int j = 0; j < TN; j++) acc[i][j] = 0.0f;

    for (int k0 = 0; k0 < K; k0 += BK) {
        float4 av = *(const float4*)&A[(long)(row0 + aRow) * lda + k0 + aCol];
        As[aCol + 0][aRow] = av.x;
        As[aCol + 1][aRow] = av.y;
        As[aCol + 2][aRow] = av.z;
        As[aCol + 3][aRow] = av.w;
        if (bOk) {
            float4 bv = *(const float4*)&Bw[(long)(k0 + bRow) * ldb + col0 + bCol];
            *(float4*)&Bs[bRow][bCol] = bv;
        }
        __syncthreads();

        #pragma unroll
        for (int kk = 0; kk < BK; kk++) {
            float4 a0 = *(const float4*)&As[kk][ty * TM];
            float4 a1 = *(const float4*)&As[kk][ty * TM + 4];
            float4 b0 = *(const float4*)&Bs[kk][tx * TN];
            float4 b1 = *(const float4*)&Bs[kk][tx * TN + 4];
            float ra[TM] = {a0.x, a0.y, a0.z, a0.w, a1.x, a1.y, a1.z, a1.w};
            float rbv[TN] = {b0.x, b0.y, b0.z, b0.w, b1.x, b1.y, b1.z, b1.w};
            #pragma unroll
            for (int i = 0; i < TM; i++)
                #pragma unroll
                for (int j = 0; j < TN; j++)
                    acc[i][j] += ra[i] * rbv[j];
        }
        __syncthreads();
    }

    #pragma unroll
    for (int i = 0; i < TM; i++) {
        long rr = row0 + ty * TM + i;
        #pragma unroll
        for (int j0 = 0; j0 < TN; j0 += 4) {
            int c = col0 + tx * TN + j0;
            if (c < N) {
                float4 v;
                v.x = acc[i][j0 + 0] + bias[c + 0];
                v.y = acc[i][j0 + 1] + bias[c + 1];
                v.z = acc[i][j0 + 2] + bias[c + 2];
                v.w = acc[i][j0 + 3] + bias[c + 3];
                if (relu) {
                    v.x = fmaxf(v.x, 0.f); v.y = fmaxf(v.y, 0.f);
                    v.z = fmaxf(v.z, 0.f); v.w = fmaxf(v.w, 0.f);
                }
                *(float4*)&C[rr * ldc + c] = v;
            }
        }
    }
}

// ---------------------------------------------------------------------------
__global__ void gate2_softmax_kernel(const float* __restrict__ W2,
                                     const float* __restrict__ b2) {
    int t = blockIdx.y;
    __shared__ float sW[GHn * NEXP];
    __shared__ float sb[NEXP];
    for (int i = threadIdx.x; i < GHn * NEXP; i += blockDim.x)
        sW[i] = W2[(size_t)t * GHn * NEXP + i];
    if (threadIdx.x < NEXP) sb[threadIdx.x] = b2[t * NEXP + threadIdx.x];
    __syncthreads();

    int b = blockIdx.x * blockDim.x + threadIdx.x;
    if (b >= Bn) return;

    const float4* gr = (const float4*)(g_gh + ((size_t)b * Tn + t) * GHn);
    float acc[NEXP];
    #pragma unroll
    for (int k = 0; k < NEXP; k++) acc[k] = sb[k];
    for (int h4 = 0; h4 < GHn / 4; h4++) {
        float4 x = gr[h4];
        const float* w = sW + h4 * 4 * NEXP;
        #pragma unroll
        for (int k = 0; k < NEXP; k++)
            acc[k] += x.x * w[k] + x.y * w[NEXP + k]
                    + x.z * w[2 * NEXP + k] + x.w * w[3 * NEXP + k];
    }
    float mx = acc[0];
    #pragma unroll
    for (int k = 1; k < NEXP; k++) mx = fmaxf(mx, acc[k]);
    float sum = 0.f;
    #pragma unroll
    for (int k = 0; k < NEXP; k++) { acc[k] = expf(acc[k] - mx); sum += acc[k]; }
    float inv = 1.0f / sum;
    float* o = g_gw + ((size_t)b * Tn + t) * NEXP;
    #pragma unroll
    for (int k = 0; k < NEXP; k++) o[k] = acc[k] * inv;
}

// ---------------------------------------------------------------------------
__global__ void agg_kernel() {
    int b = blockIdx.x;
    int e = threadIdx.x;
    __shared__ float sgw[Tn * NEXP];
    if (threadIdx.x < Tn * NEXP)
        sgw[threadIdx.x] = g_gw[(size_t)b * Tn * NEXP + threadIdx.x];
    __syncthreads();
    const float* eb = g_emb + (size_t)b * NEXP * En + e;
    float a0 = 0.f, a1 = 0.f, a2 = 0.f;
    #pragma unroll
    for (int k = 0; k < NEXP; k++) {
        float v = eb[(size_t)k * En];
        a0 += sgw[k] * v;
        a1 += sgw[NEXP + k] * v;
        a2 += sgw[2 * NEXP + k] * v;
    }
    float* o = g_agg + (size_t)b * Tn * En + e;
    o[0]      = a0;
    o[En]     = a1;
    o[2 * En] = a2;
}

// ---------------------------------------------------------------------------
extern "C" void kernel_launch(void* const* d_in, const int* in_sizes, int n_in,
                              void* d_out, int out_size) {
    const float* inputs = (const float*)d_in[0];
    const float* eW1 = (const float*)d_in[1];
    const float* eb1 = (const float*)d_in[2];
    const float* eW2 = (const float*)d_in[3];
    const float* eb2 = (const float*)d_in[4];
    const float* gW1 = (const float*)d_in[5];
    const float* gb1 = (const float*)d_in[6];
    const float* gW2 = (const float*)d_in[7];
    const float* gb2 = (const float*)d_in[8];
    const float* tW1 = (const float*)d_in[9];
    const float* tb1 = (const float*)d_in[10];
    const float* tW2 = (const float*)d_in[11];
    const float* tb2 = (const float*)d_in[12];
    float* out = (float*)d_out;

    __half *p_in, *p_gin, *p_h1, *p_we1, *p_we2, *p_wg1;
    float *p_emb, *p_gh, *p_agg, *p_th;
    cudaGetSymbolAddress((void**)&p_in,  s_in);
    cudaGetSymbolAddress((void**)&p_gin, s_gin);
    cudaGetSymbolAddress((void**)&p_h1,  s_h1);
    cudaGetSymbolAddress((void**)&p_we1, s_we1);
    cudaGetSymbolAddress((void**)&p_we2, s_we2);
    cudaGetSymbolAddress((void**)&p_wg1, s_wg1);
    cudaGetSymbolAddress((void**)&p_emb, g_emb);
    cudaGetSymbolAddress((void**)&p_gh,  g_gh);
    cudaGetSymbolAddress((void**)&p_agg, g_agg);
    cudaGetSymbolAddress((void**)&p_th,  g_th);

    cudaFuncSetAttribute(tc_gemm, cudaFuncAttributeMaxDynamicSharedMemorySize, TC_SMEM);

    // ---- one-time conversions ----
    conv_half<<<(Bn * Gn * Dn / 4 + 255) / 256, 256>>>(inputs, p_in, Bn * Gn * Dn / 4);
    conv_gin<<<(Bn * Tn * Dn / 4 + 255) / 256, 256>>>(inputs);
    conv_half<<<(NEXP * Dn * Hn / 4 + 255) / 256, 256>>>(eW1, p_we1, NEXP * Dn * Hn / 4);
    conv_half<<<(NEXP * Hn * En / 4 + 255) / 256, 256>>>(eW2, p_we2, NEXP * Hn * En / 4);
    conv_half<<<(Tn * Dn * GHn / 4 + 255) / 256, 256>>>(gW1, p_wg1, Tn * Dn * GHn / 4);

    // ---- expert layer 1: h1(fp16) = relu(in @ eW1 + b1) ----
    tc_gemm<<<dim3(Bn / 128, Hn / 128, NEXP), 256, TC_SMEM>>>(
        p_in, p_we1, eb1,
        nullptr, p_h1,
        Dn, Gn * Dn, Hn, NEXP * Hn,
        (long)Dn, NEn, (long)Dn * Hn, (long)Hn, (long)Hn, 1, 1);

    // ---- expert layer 2: emb(fp32) = h1 @ eW2 + b2 ----
    tc_gemm<<<dim3(Bn / 128, En / 128, NEXP), 256, TC_SMEM>>>(
        p_h1, p_we2, eb2,
        p_emb, nullptr,
        Hn, NEXP * Hn, En, NEXP * En,
        (long)Hn, 1, (long)Hn * En, (long)En, (long)En, 0, 0);

    // ---- gate layer 1: gh(fp32) = relu(gin @ gW1 + b1) ----
    tc_gemm<<<dim3(Bn / 128, GHn / 128, Tn), 256, TC_SMEM>>>(
        p_gin, p_wg1, gb1,
        p_gh, nullptr,
        Dn, Tn * Dn, GHn, Tn * GHn,
        (long)Dn, 1, (long)Dn * GHn, (long)GHn, (long)GHn, 1, 0);

    gate2_softmax_kernel<<<dim3(Bn / 256, Tn), 256>>>(gW2, gb2);

    agg_kernel<<<Bn, En>>>();

    sgemm_bias<<<dim3(Bn / BM, 1, Tn), 256>>>(
        p_agg, tW1, tb1, p_th,
        THn, En, Tn * En, THn, Tn * THn,
        (long)En, 1, (long)En * THn, (long)THn, (long)THn, 1);

    sgemm_bias<<<dim3(Bn / BM, 1, Tn), 256>>>(
        p_th, tW2, tb2, out,
        TOn, THn, Tn * THn, TOn, Tn * TOn,
        (long)THn, 1, (long)THn * TOn, (long)TOn, (long)TOn, 0);
}